// round 1
// baseline (speedup 1.0000x reference)
#include <cuda_runtime.h>
#include <cuda_bf16.h>
#include <math.h>

// Problem constants
#define BATCH 2
#define SEQ   2048
#define DMODEL 1024
#define NHEAD 16
#define DK    64
#define DFF   4096
#define MTOK  (BATCH * SEQ)           // 4096 tokens
#define LN_EPS 1e-5f

// ---------------- scratch (device globals; no allocation allowed) ----------
__device__ float g_xn  [(size_t)MTOK * DMODEL];   // 16 MB   layernorm output
__device__ float g_q   [(size_t)MTOK * DMODEL];   // 16 MB
__device__ float g_k   [(size_t)MTOK * DMODEL];   // 16 MB
__device__ float g_v   [(size_t)MTOK * DMODEL];   // 16 MB
__device__ float g_attn[(size_t)MTOK * DMODEL];   // 16 MB   attention context
__device__ float g_x1  [(size_t)MTOK * DMODEL];   // 16 MB   residual-1 output
__device__ float g_ff  [(size_t)MTOK * DFF];      // 64 MB   FFN hidden
__device__ float g_scores[(size_t)BATCH * NHEAD * SEQ * SEQ]; // 512 MB

// ---------------------------------------------------------------------------
// LayerNorm: one block per row of DMODEL=1024. torch-style: unbiased variance
// (ddof=1), eps added to STD. alpha/bias are scalars.
// ---------------------------------------------------------------------------
__global__ void ln_kernel(const float* __restrict__ x, float* __restrict__ y,
                          const float* __restrict__ alpha, const float* __restrict__ beta)
{
    const size_t r = blockIdx.x;
    const float* xr = x + r * DMODEL;
    float* yr = y + r * DMODEL;
    const int t = threadIdx.x;   // 256 threads, 4 elements each

    float v[4];
    float s = 0.f, ss = 0.f;
#pragma unroll
    for (int it = 0; it < 4; it++) {
        float a = xr[t + it * 256];
        v[it] = a;
        s += a;
        ss += a * a;
    }
    // block reduce (s, ss)
    __shared__ float red[2][32];
    const int lane = t & 31, wid = t >> 5;
#pragma unroll
    for (int o = 16; o > 0; o >>= 1) {
        s  += __shfl_down_sync(0xffffffffu, s,  o);
        ss += __shfl_down_sync(0xffffffffu, ss, o);
    }
    if (lane == 0) { red[0][wid] = s; red[1][wid] = ss; }
    __syncthreads();
    if (wid == 0) {
        s  = (lane < 8) ? red[0][lane] : 0.f;
        ss = (lane < 8) ? red[1][lane] : 0.f;
#pragma unroll
        for (int o = 4; o > 0; o >>= 1) {
            s  += __shfl_down_sync(0xffffffffu, s,  o);
            ss += __shfl_down_sync(0xffffffffu, ss, o);
        }
        if (lane == 0) { red[0][0] = s; red[1][0] = ss; }
    }
    __syncthreads();
    s = red[0][0]; ss = red[1][0];

    const float mean = s * (1.0f / DMODEL);
    float var = (ss - s * mean) * (1.0f / (DMODEL - 1));
    var = fmaxf(var, 0.f);
    const float inv = alpha[0] / (sqrtf(var) + LN_EPS);
    const float b0 = beta[0];
#pragma unroll
    for (int it = 0; it < 4; it++)
        yr[t + it * 256] = (v[it] - mean) * inv + b0;
}

// ---------------------------------------------------------------------------
// Dense GEMM: C[M,N] = A[M,K] @ W[N,K]^T + bias[n]  (+relu) (+residual[m,n])
// 128x128 tile, BK=8, 256 threads, 8x8 per thread, float4 global loads.
// Requires M%128==0, N%128==0, K%8==0 (true for all uses here).
// EPI: 0 = bias, 1 = bias+relu, 2 = bias+residual
// ---------------------------------------------------------------------------
template <int EPI>
__global__ __launch_bounds__(256) void gemm_kernel(
    const float* __restrict__ A, const float* __restrict__ W,
    const float* __restrict__ bias, const float* __restrict__ res,
    float* __restrict__ C, int M, int N, int K)
{
    __shared__ float As[8][128];
    __shared__ float Bs[8][128];

    const int tid = threadIdx.x;
    const int bm = blockIdx.y * 128;
    const int bn = blockIdx.x * 128;

    const int lrow = tid >> 1;           // 0..127
    const int lcol = (tid & 1) * 4;      // 0 or 4
    const float* Aptr = A + (size_t)(bm + lrow) * K + lcol;
    const float* Wptr = W + (size_t)(bn + lrow) * K + lcol;

    const int tx = tid & 15;             // 0..15  -> N direction
    const int ty = tid >> 4;             // 0..15  -> M direction

    float acc[8][8];
#pragma unroll
    for (int i = 0; i < 8; i++)
#pragma unroll
        for (int j = 0; j < 8; j++) acc[i][j] = 0.f;

    for (int k0 = 0; k0 < K; k0 += 8) {
        float4 av = *(const float4*)(Aptr + k0);
        float4 wv = *(const float4*)(Wptr + k0);
        As[lcol + 0][lrow] = av.x; As[lcol + 1][lrow] = av.y;
        As[lcol + 2][lrow] = av.z; As[lcol + 3][lrow] = av.w;
        Bs[lcol + 0][lrow] = wv.x; Bs[lcol + 1][lrow] = wv.y;
        Bs[lcol + 2][lrow] = wv.z; Bs[lcol + 3][lrow] = wv.w;
        __syncthreads();
#pragma unroll
        for (int k = 0; k < 8; k++) {
            float a[8], b[8];
#pragma unroll
            for (int i = 0; i < 8; i++) a[i] = As[k][ty * 8 + i];
#pragma unroll
            for (int j = 0; j < 8; j++) b[j] = Bs[k][tx * 8 + j];
#pragma unroll
            for (int i = 0; i < 8; i++)
#pragma unroll
                for (int j = 0; j < 8; j++) acc[i][j] = fmaf(a[i], b[j], acc[i][j]);
        }
        __syncthreads();
    }

    float bcol[8];
#pragma unroll
    for (int j = 0; j < 8; j++) bcol[j] = bias[bn + tx * 8 + j];

#pragma unroll
    for (int i = 0; i < 8; i++) {
        const int m = bm + ty * 8 + i;
        float* crow = C + (size_t)m * N + bn + tx * 8;
        const float* rrow = (EPI == 2) ? (res + (size_t)m * N + bn + tx * 8) : nullptr;
#pragma unroll
        for (int j = 0; j < 8; j++) {
            float v = acc[i][j] + bcol[j];
            if (EPI == 1) v = fmaxf(v, 0.f);
            if (EPI == 2) v += rrow[j];
            crow[j] = v;
        }
    }
}

// ---------------------------------------------------------------------------
// Attention scores: scores[bh, i, j] = (1/8) * sum_d Q[b,i,h,d] * K[b,j,h,d]
// q/k stored as [M, DMODEL] = [b*S+s, h*DK+d]. 64x64 tile per block, BK=16.
// grid: (S/64, S/64, B*H), 256 threads, 4x4 per thread.
// ---------------------------------------------------------------------------
__global__ __launch_bounds__(256) void scores_kernel(
    const float* __restrict__ q, const float* __restrict__ k,
    float* __restrict__ scores)
{
    const int bh = blockIdx.z;
    const int b  = bh / NHEAD;
    const int h  = bh % NHEAD;
    const float* Q  = q + (size_t)b * SEQ * DMODEL + h * DK;
    const float* Kp = k + (size_t)b * SEQ * DMODEL + h * DK;

    __shared__ float Qs[16][64];
    __shared__ float Ks[16][64];

    const int tid = threadIdx.x;
    const int ti = blockIdx.y * 64;
    const int tj = blockIdx.x * 64;
    const int lr = tid >> 2;            // 0..63
    const int lc = (tid & 3) * 4;       // 0,4,8,12
    const int tx = tid & 15, ty = tid >> 4;

    float acc[4][4];
#pragma unroll
    for (int i = 0; i < 4; i++)
#pragma unroll
        for (int j = 0; j < 4; j++) acc[i][j] = 0.f;

#pragma unroll
    for (int kk = 0; kk < DK; kk += 16) {
        float4 qv = *(const float4*)(Q  + (size_t)(ti + lr) * DMODEL + kk + lc);
        float4 kv = *(const float4*)(Kp + (size_t)(tj + lr) * DMODEL + kk + lc);
        Qs[lc + 0][lr] = qv.x; Qs[lc + 1][lr] = qv.y;
        Qs[lc + 2][lr] = qv.z; Qs[lc + 3][lr] = qv.w;
        Ks[lc + 0][lr] = kv.x; Ks[lc + 1][lr] = kv.y;
        Ks[lc + 2][lr] = kv.z; Ks[lc + 3][lr] = kv.w;
        __syncthreads();
#pragma unroll
        for (int p = 0; p < 16; p++) {
            float a[4], bb[4];
#pragma unroll
            for (int i = 0; i < 4; i++) a[i]  = Qs[p][ty * 4 + i];
#pragma unroll
            for (int j = 0; j < 4; j++) bb[j] = Ks[p][tx * 4 + j];
#pragma unroll
            for (int i = 0; i < 4; i++)
#pragma unroll
                for (int j = 0; j < 4; j++) acc[i][j] = fmaf(a[i], bb[j], acc[i][j]);
        }
        __syncthreads();
    }

#pragma unroll
    for (int i = 0; i < 4; i++) {
        float* out = scores + ((size_t)bh * SEQ + ti + ty * 4 + i) * SEQ + tj + tx * 4;
#pragma unroll
        for (int j = 0; j < 4; j++) out[j] = acc[i][j] * 0.125f;   // 1/sqrt(64)
    }
}

// ---------------------------------------------------------------------------
// Softmax over last dim with mask. One block per (bh, i) row of length SEQ.
// mask layout [B,1,1,SEQ] -> mask[b*SEQ + j]; masked -> -1e9 before max.
// ---------------------------------------------------------------------------
__global__ void softmax_kernel(float* __restrict__ scores, const int* __restrict__ mask)
{
    const size_t r = blockIdx.x;                  // 0 .. B*H*SEQ-1
    const int b = (int)(r / ((size_t)NHEAD * SEQ));
    float* row = scores + r * SEQ;
    const int* mrow = mask + (size_t)b * SEQ;
    const int t = threadIdx.x;                    // 256 threads, 8 each

    float vals[8];
    float mx = -3.402823e38f;
#pragma unroll
    for (int it = 0; it < 8; it++) {
        const int j = t + it * 256;
        float v = row[j];
        if (mrow[j] == 0) v = -1e9f;
        vals[it] = v;
        mx = fmaxf(mx, v);
    }
    __shared__ float red[32];
    const int lane = t & 31, wid = t >> 5;
#pragma unroll
    for (int o = 16; o > 0; o >>= 1) mx = fmaxf(mx, __shfl_xor_sync(0xffffffffu, mx, o));
    if (lane == 0) red[wid] = mx;
    __syncthreads();
    if (wid == 0) {
        mx = (lane < 8) ? red[lane] : -3.402823e38f;
#pragma unroll
        for (int o = 4; o > 0; o >>= 1) mx = fmaxf(mx, __shfl_xor_sync(0xffffffffu, mx, o));
        if (lane == 0) red[0] = mx;
    }
    __syncthreads();
    mx = red[0];

    float sum = 0.f;
#pragma unroll
    for (int it = 0; it < 8; it++) {
        const float e = __expf(vals[it] - mx);
        vals[it] = e;
        sum += e;
    }
    __syncthreads();
#pragma unroll
    for (int o = 16; o > 0; o >>= 1) sum += __shfl_xor_sync(0xffffffffu, sum, o);
    if (lane == 0) red[wid] = sum;
    __syncthreads();
    if (wid == 0) {
        sum = (lane < 8) ? red[lane] : 0.f;
#pragma unroll
        for (int o = 4; o > 0; o >>= 1) sum += __shfl_xor_sync(0xffffffffu, sum, o);
        if (lane == 0) red[0] = sum;
    }
    __syncthreads();
    const float inv = 1.0f / red[0];
#pragma unroll
    for (int it = 0; it < 8; it++) row[t + it * 256] = vals[it] * inv;
}

// ---------------------------------------------------------------------------
// PV: out[b, i, h, d] = sum_j P[bh, i, j] * V[b, j, h, d]
// out written to [M, DMODEL] layout. 64 (i) x 64 (d=DK) tile, BK=16 over j.
// grid: (1, S/64, B*H), 256 threads, 4x4 per thread.
// ---------------------------------------------------------------------------
__global__ __launch_bounds__(256) void pv_kernel(
    const float* __restrict__ P, const float* __restrict__ v,
    float* __restrict__ out)
{
    const int bh = blockIdx.z;
    const int b  = bh / NHEAD;
    const int h  = bh % NHEAD;
    const float* Pp = P + (size_t)bh * SEQ * SEQ;
    const float* V  = v + (size_t)b * SEQ * DMODEL + h * DK;

    __shared__ float Ps[16][64];
    __shared__ float Vs[16][64];

    const int tid = threadIdx.x;
    const int ti = blockIdx.y * 64;
    const int lr = tid >> 2;            // P: row 0..63
    const int lc = (tid & 3) * 4;       // P: col in j-chunk
    const int vr = tid >> 4;            // V: row 0..15 in j-chunk
    const int vc = (tid & 15) * 4;      // V: col 0..63
    const int tx = tid & 15, ty = tid >> 4;

    float acc[4][4];
#pragma unroll
    for (int i = 0; i < 4; i++)
#pragma unroll
        for (int j = 0; j < 4; j++) acc[i][j] = 0.f;

    for (int j0 = 0; j0 < SEQ; j0 += 16) {
        float4 p4 = *(const float4*)(Pp + (size_t)(ti + lr) * SEQ + j0 + lc);
        Ps[lc + 0][lr] = p4.x; Ps[lc + 1][lr] = p4.y;
        Ps[lc + 2][lr] = p4.z; Ps[lc + 3][lr] = p4.w;
        *(float4*)&Vs[vr][vc] = *(const float4*)(V + (size_t)(j0 + vr) * DMODEL + vc);
        __syncthreads();
#pragma unroll
        for (int p = 0; p < 16; p++) {
            float a[4], bb[4];
#pragma unroll
            for (int i = 0; i < 4; i++) a[i]  = Ps[p][ty * 4 + i];
#pragma unroll
            for (int j = 0; j < 4; j++) bb[j] = Vs[p][tx * 4 + j];
#pragma unroll
            for (int i = 0; i < 4; i++)
#pragma unroll
                for (int j = 0; j < 4; j++) acc[i][j] = fmaf(a[i], bb[j], acc[i][j]);
        }
        __syncthreads();
    }

#pragma unroll
    for (int i = 0; i < 4; i++) {
        float* orow = out + (size_t)(b * SEQ + ti + ty * 4 + i) * DMODEL + h * DK + tx * 4;
#pragma unroll
        for (int j = 0; j < 4; j++) orow[j] = acc[i][j];
    }
}

// ---------------------------------------------------------------------------
// Launch sequence
// ---------------------------------------------------------------------------
extern "C" void kernel_launch(void* const* d_in, const int* in_sizes, int n_in,
                              void* d_out, int out_size)
{
    const float* x    = (const float*)d_in[0];
    const int*   mask = (const int*)  d_in[1];
    const float* wq   = (const float*)d_in[2];
    const float* bq   = (const float*)d_in[3];
    const float* wk   = (const float*)d_in[4];
    const float* bk   = (const float*)d_in[5];
    const float* wv   = (const float*)d_in[6];
    const float* bv   = (const float*)d_in[7];
    const float* wo   = (const float*)d_in[8];
    const float* bo   = (const float*)d_in[9];
    const float* w1   = (const float*)d_in[10];
    const float* b1   = (const float*)d_in[11];
    const float* w2   = (const float*)d_in[12];
    const float* b2   = (const float*)d_in[13];
    const float* a1   = (const float*)d_in[14];
    const float* n1   = (const float*)d_in[15];
    const float* a2   = (const float*)d_in[16];
    const float* n2   = (const float*)d_in[17];
    float* out = (float*)d_out;

    float *xn, *q, *k, *v, *attn, *x1, *ff, *scores;
    cudaGetSymbolAddress((void**)&xn,     g_xn);
    cudaGetSymbolAddress((void**)&q,      g_q);
    cudaGetSymbolAddress((void**)&k,      g_k);
    cudaGetSymbolAddress((void**)&v,      g_v);
    cudaGetSymbolAddress((void**)&attn,   g_attn);
    cudaGetSymbolAddress((void**)&x1,     g_x1);
    cudaGetSymbolAddress((void**)&ff,     g_ff);
    cudaGetSymbolAddress((void**)&scores, g_scores);

    // --- residual 1: pre-norm + attention ---
    ln_kernel<<<MTOK, 256>>>(x, xn, a1, n1);

    dim3 g1024(DMODEL / 128, MTOK / 128);      // (8, 32)
    gemm_kernel<0><<<g1024, 256>>>(xn, wq, bq, nullptr, q, MTOK, DMODEL, DMODEL);
    gemm_kernel<0><<<g1024, 256>>>(xn, wk, bk, nullptr, k, MTOK, DMODEL, DMODEL);
    gemm_kernel<0><<<g1024, 256>>>(xn, wv, bv, nullptr, v, MTOK, DMODEL, DMODEL);

    dim3 gsc(SEQ / 64, SEQ / 64, BATCH * NHEAD);   // (32, 32, 32)
    scores_kernel<<<gsc, 256>>>(q, k, scores);

    softmax_kernel<<<BATCH * NHEAD * SEQ, 256>>>(scores, mask);

    dim3 gpv(1, SEQ / 64, BATCH * NHEAD);          // (1, 32, 32)
    pv_kernel<<<gpv, 256>>>(scores, v, attn);

    gemm_kernel<2><<<g1024, 256>>>(attn, wo, bo, x, x1, MTOK, DMODEL, DMODEL);

    // --- residual 2: pre-norm + FFN ---
    ln_kernel<<<MTOK, 256>>>(x1, xn, a2, n2);

    dim3 gff1(DFF / 128, MTOK / 128);              // (32, 32)
    gemm_kernel<1><<<gff1, 256>>>(xn, w1, b1, nullptr, ff, MTOK, DFF, DMODEL);

    dim3 gff2(DMODEL / 128, MTOK / 128);           // (8, 32)
    gemm_kernel<2><<<gff2, 256>>>(ff, w2, b2, x1, out, MTOK, DMODEL, DFF);
}

// round 4
// speedup vs baseline: 2.5598x; 2.5598x over previous
#include <cuda_runtime.h>
#include <cuda_bf16.h>
#include <math.h>
#include <stdint.h>

// Problem constants
#define BATCH 2
#define SEQ   2048
#define DMODEL 1024
#define NHEAD 16
#define DK    64
#define DFF   4096
#define MTOK  (BATCH * SEQ)           // 4096 tokens
#define LN_EPS 1e-5f

// ---------------- scratch (device globals; no allocation allowed) ----------
__device__ float g_xn  [(size_t)MTOK * DMODEL];
__device__ float g_q   [(size_t)MTOK * DMODEL];
__device__ float g_k   [(size_t)MTOK * DMODEL];
__device__ float g_v   [(size_t)MTOK * DMODEL];
__device__ float g_attn[(size_t)MTOK * DMODEL];
__device__ float g_x1  [(size_t)MTOK * DMODEL];
__device__ float g_ff  [(size_t)MTOK * DFF];
__device__ float g_scores[(size_t)BATCH * NHEAD * SEQ * SEQ]; // 512 MB

// ============================ helpers ======================================
__device__ __forceinline__ uint32_t smem_u32(const void* p) {
    uint32_t a;
    asm("{ .reg .u64 t; cvta.to.shared.u64 t, %1; cvt.u32.u64 %0, t; }"
        : "=r"(a) : "l"(p));
    return a;
}

__device__ __forceinline__ uint32_t f2tf32(float f) {
    uint32_t r;
    asm("cvt.rna.tf32.f32 %0, %1;" : "=r"(r) : "f"(f));
    return r;
}

__device__ __forceinline__ void mma_tf32(float* c, const uint32_t* a, const uint32_t* b) {
    asm volatile(
        "mma.sync.aligned.m16n8k8.row.col.f32.tf32.tf32.f32 "
        "{%0,%1,%2,%3}, {%4,%5,%6,%7}, {%8,%9}, {%0,%1,%2,%3};"
        : "+f"(c[0]), "+f"(c[1]), "+f"(c[2]), "+f"(c[3])
        : "r"(a[0]), "r"(a[1]), "r"(a[2]), "r"(a[3]),
          "r"(b[0]), "r"(b[1]));
}

// ---------------------------------------------------------------------------
// LayerNorm: one block per row, torch semantics (ddof=1, eps on std).
// ---------------------------------------------------------------------------
__global__ void ln_kernel(const float* __restrict__ x, float* __restrict__ y,
                          const float* __restrict__ alpha, const float* __restrict__ beta)
{
    const size_t r = blockIdx.x;
    const float* xr = x + r * DMODEL;
    float* yr = y + r * DMODEL;
    const int t = threadIdx.x;

    float v[4];
    float s = 0.f, ss = 0.f;
#pragma unroll
    for (int it = 0; it < 4; it++) {
        float a = xr[t + it * 256];
        v[it] = a;
        s += a;
        ss += a * a;
    }
    __shared__ float red[2][32];
    const int lane = t & 31, wid = t >> 5;
#pragma unroll
    for (int o = 16; o > 0; o >>= 1) {
        s  += __shfl_down_sync(0xffffffffu, s,  o);
        ss += __shfl_down_sync(0xffffffffu, ss, o);
    }
    if (lane == 0) { red[0][wid] = s; red[1][wid] = ss; }
    __syncthreads();
    if (wid == 0) {
        s  = (lane < 8) ? red[0][lane] : 0.f;
        ss = (lane < 8) ? red[1][lane] : 0.f;
#pragma unroll
        for (int o = 4; o > 0; o >>= 1) {
            s  += __shfl_down_sync(0xffffffffu, s,  o);
            ss += __shfl_down_sync(0xffffffffu, ss, o);
        }
        if (lane == 0) { red[0][0] = s; red[1][0] = ss; }
    }
    __syncthreads();
    s = red[0][0]; ss = red[1][0];

    const float mean = s * (1.0f / DMODEL);
    float var = (ss - s * mean) * (1.0f / (DMODEL - 1));
    var = fmaxf(var, 0.f);
    const float inv = alpha[0] / (sqrtf(var) + LN_EPS);
    const float b0 = beta[0];
#pragma unroll
    for (int it = 0; it < 4; it++)
        yr[t + it * 256] = (v[it] - mean) * inv + b0;
}

// ---------------------------------------------------------------------------
// Generalized GEMM on mma.sync tf32:
//   C[M,N](ldc) = op( A[M,K](lda) @ B[N,K](ldb)^T )
// Block tile 128x128, BK=32, 256 threads = 8 warps (2Mx4N), warp 64x32.
// Single SMEM buffer with register prefetch of next chunk.
// EPI: 0 = +bias, 1 = +bias,relu, 2 = +bias,+residual, 3 = *scale
// ---------------------------------------------------------------------------
template <int EPI>
__global__ __launch_bounds__(256) void gemm_mma(
    const float* __restrict__ A, const float* __restrict__ B,
    const float* __restrict__ bias, const float* __restrict__ res,
    float* __restrict__ C, int M, int N, int K,
    int lda, int ldb, int ldc, float scale,
    size_t sAz, size_t sBz, size_t sCz)
{
    A += blockIdx.z * sAz;
    B += blockIdx.z * sBz;
    C += blockIdx.z * sCz;

    __shared__ uint32_t As[128 * 36];   // [row][36], pad 4 -> conflict-free
    __shared__ uint32_t Bs[128 * 36];

    const int tid = threadIdx.x;
    const int lane = tid & 31, wid = tid >> 5;
    const int bm = blockIdx.y * 128, bn = blockIdx.x * 128;
    const int wm0 = (wid >> 2) * 64;
    const int wn0 = (wid & 3) * 32;

    const uint32_t as_base = smem_u32(As);
    const uint32_t bs_base = smem_u32(Bs);

    const int lm = tid >> 3;              // 0..31 (rows lm, lm+32, lm+64, lm+96)
    const int lks = tid & 7;              // 16B slot within 32-float k-chunk

    float4 pa[4], pb[4];
    const int NC = K >> 5;

#pragma unroll
    for (int i = 0; i < 4; i++) {
        const int m = lm + i * 32;
        pa[i] = *(const float4*)(A + (size_t)(bm + m) * lda + lks * 4);
        pb[i] = *(const float4*)(B + (size_t)(bn + m) * ldb + lks * 4);
    }
#pragma unroll
    for (int i = 0; i < 4; i++) {
        const int m = lm + i * 32;
        const uint32_t off = (uint32_t)(m * 36 + lks * 4) * 4u;
        asm volatile("st.shared.v4.b32 [%0], {%1,%2,%3,%4};" ::
            "r"(as_base + off), "r"(f2tf32(pa[i].x)), "r"(f2tf32(pa[i].y)),
            "r"(f2tf32(pa[i].z)), "r"(f2tf32(pa[i].w)) : "memory");
        asm volatile("st.shared.v4.b32 [%0], {%1,%2,%3,%4};" ::
            "r"(bs_base + off), "r"(f2tf32(pb[i].x)), "r"(f2tf32(pb[i].y)),
            "r"(f2tf32(pb[i].z)), "r"(f2tf32(pb[i].w)) : "memory");
    }
    __syncthreads();

    float acc[4][4][4];
#pragma unroll
    for (int mt = 0; mt < 4; mt++)
#pragma unroll
        for (int nt = 0; nt < 4; nt++)
#pragma unroll
            for (int j = 0; j < 4; j++) acc[mt][nt][j] = 0.f;

    for (int c = 0; c < NC; c++) {
        if (c + 1 < NC) {
#pragma unroll
            for (int i = 0; i < 4; i++) {
                const int m = lm + i * 32;
                pa[i] = *(const float4*)(A + (size_t)(bm + m) * lda + (c + 1) * 32 + lks * 4);
                pb[i] = *(const float4*)(B + (size_t)(bn + m) * ldb + (c + 1) * 32 + lks * 4);
            }
        }
#pragma unroll
        for (int ks = 0; ks < 4; ks++) {
            const int kc = ks * 8 + (lane & 3);
            uint32_t afr[4][4], bfr[4][2];
#pragma unroll
            for (int mt = 0; mt < 4; mt++) {
                const int rm = wm0 + mt * 16 + (lane >> 2);
                afr[mt][0] = As[rm * 36 + kc];
                afr[mt][1] = As[(rm + 8) * 36 + kc];
                afr[mt][2] = As[rm * 36 + kc + 4];
                afr[mt][3] = As[(rm + 8) * 36 + kc + 4];
            }
#pragma unroll
            for (int nt = 0; nt < 4; nt++) {
                const int rn = wn0 + nt * 8 + (lane >> 2);
                bfr[nt][0] = Bs[rn * 36 + kc];
                bfr[nt][1] = Bs[rn * 36 + kc + 4];
            }
#pragma unroll
            for (int mt = 0; mt < 4; mt++)
#pragma unroll
                for (int nt = 0; nt < 4; nt++)
                    mma_tf32(acc[mt][nt], afr[mt], bfr[nt]);
        }
        __syncthreads();
        if (c + 1 < NC) {
#pragma unroll
            for (int i = 0; i < 4; i++) {
                const int m = lm + i * 32;
                const uint32_t off = (uint32_t)(m * 36 + lks * 4) * 4u;
                asm volatile("st.shared.v4.b32 [%0], {%1,%2,%3,%4};" ::
                    "r"(as_base + off), "r"(f2tf32(pa[i].x)), "r"(f2tf32(pa[i].y)),
                    "r"(f2tf32(pa[i].z)), "r"(f2tf32(pa[i].w)) : "memory");
                asm volatile("st.shared.v4.b32 [%0], {%1,%2,%3,%4};" ::
                    "r"(bs_base + off), "r"(f2tf32(pb[i].x)), "r"(f2tf32(pb[i].y)),
                    "r"(f2tf32(pb[i].z)), "r"(f2tf32(pb[i].w)) : "memory");
            }
            __syncthreads();
        }
    }

#pragma unroll
    for (int mt = 0; mt < 4; mt++) {
        const int row = bm + wm0 + mt * 16 + (lane >> 2);
#pragma unroll
        for (int nt = 0; nt < 4; nt++) {
            const int col = bn + wn0 + nt * 8 + 2 * (lane & 3);
            float b0 = 0.f, b1 = 0.f;
            if (EPI != 3) { b0 = bias[col]; b1 = bias[col + 1]; }
#pragma unroll
            for (int half = 0; half < 2; half++) {
                const int r = row + half * 8;
                float v0 = acc[mt][nt][half * 2 + 0];
                float v1 = acc[mt][nt][half * 2 + 1];
                if (EPI == 3) { v0 *= scale; v1 *= scale; }
                else          { v0 += b0;   v1 += b1;   }
                if (EPI == 1) { v0 = fmaxf(v0, 0.f); v1 = fmaxf(v1, 0.f); }
                if (EPI == 2) {
                    const float* rr = res + (size_t)r * ldc + col;
                    v0 += rr[0]; v1 += rr[1];
                }
                float* cr = C + (size_t)r * ldc + col;
                cr[0] = v0; cr[1] = v1;
            }
        }
    }
}

// ---------------------------------------------------------------------------
// PV on mma.sync tf32: out[b, i, h, :] = P[bh] @ V_h
// P: [SEQ, SEQ] (A, row-major), V_h: [SEQ, DK] k-major -> loaded transposed.
// Tile 128 (i) x 64 (d), BK=32 over j. 8 warps (4Mx2N), warp 32x32.
// grid: (1, SEQ/128, BATCH*NHEAD)
// ---------------------------------------------------------------------------
__global__ __launch_bounds__(256) void pv_mma(
    const float* __restrict__ P, const float* __restrict__ v,
    float* __restrict__ out)
{
    const int bh = blockIdx.z;
    const int b  = bh / NHEAD;
    const int h  = bh % NHEAD;
    const float* Pp = P + (size_t)bh * SEQ * SEQ;
    const float* V  = v + (size_t)b * SEQ * DMODEL + h * DK;

    __shared__ uint32_t As[128 * 36];   // P tile  [i][k]
    __shared__ uint32_t Bs[64 * 36];    // V tile  [d][k]  (transposed load)

    const int tid = threadIdx.x;
    const int lane = tid & 31, wid = tid >> 5;
    const int ti = blockIdx.y * 128;
    const int wm0 = (wid >> 1) * 32;    // 0,32,64,96
    const int wn0 = (wid & 1) * 32;     // 0,32

    const uint32_t as_base = smem_u32(As);

    const int lm = tid >> 3;            // 0..31
    const int lks = tid & 7;            // 0..7

    // B loader mapping: idx = tid + i*256 (i<2): k = idx>>4 (0..31), n4 = (idx&15)*4
    const int bk = tid >> 4;            // 0..15 -> rows bk, bk+16
    const int bn4 = (tid & 15) * 4;

    float4 pa[4], pb[2];
    const int NC = SEQ >> 5;            // 64

#pragma unroll
    for (int i = 0; i < 4; i++)
        pa[i] = *(const float4*)(Pp + (size_t)(ti + lm + i * 32) * SEQ + lks * 4);
#pragma unroll
    for (int i = 0; i < 2; i++)
        pb[i] = *(const float4*)(V + (size_t)(bk + i * 16) * DMODEL + bn4);

#pragma unroll
    for (int i = 0; i < 4; i++) {
        const uint32_t off = (uint32_t)((lm + i * 32) * 36 + lks * 4) * 4u;
        asm volatile("st.shared.v4.b32 [%0], {%1,%2,%3,%4};" ::
            "r"(as_base + off), "r"(f2tf32(pa[i].x)), "r"(f2tf32(pa[i].y)),
            "r"(f2tf32(pa[i].z)), "r"(f2tf32(pa[i].w)) : "memory");
    }
#pragma unroll
    for (int i = 0; i < 2; i++) {
        const int kk = bk + i * 16;
        Bs[(bn4 + 0) * 36 + kk] = f2tf32(pb[i].x);
        Bs[(bn4 + 1) * 36 + kk] = f2tf32(pb[i].y);
        Bs[(bn4 + 2) * 36 + kk] = f2tf32(pb[i].z);
        Bs[(bn4 + 3) * 36 + kk] = f2tf32(pb[i].w);
    }
    __syncthreads();

    float acc[2][4][4];
#pragma unroll
    for (int mt = 0; mt < 2; mt++)
#pragma unroll
        for (int nt = 0; nt < 4; nt++)
#pragma unroll
            for (int j = 0; j < 4; j++) acc[mt][nt][j] = 0.f;

    for (int c = 0; c < NC; c++) {
        if (c + 1 < NC) {
#pragma unroll
            for (int i = 0; i < 4; i++)
                pa[i] = *(const float4*)(Pp + (size_t)(ti + lm + i * 32) * SEQ + (c + 1) * 32 + lks * 4);
#pragma unroll
            for (int i = 0; i < 2; i++)
                pb[i] = *(const float4*)(V + (size_t)((c + 1) * 32 + bk + i * 16) * DMODEL + bn4);
        }
#pragma unroll
        for (int ks = 0; ks < 4; ks++) {
            const int kc = ks * 8 + (lane & 3);
            uint32_t afr[2][4], bfr[4][2];
#pragma unroll
            for (int mt = 0; mt < 2; mt++) {
                const int rm = wm0 + mt * 16 + (lane >> 2);
                afr[mt][0] = As[rm * 36 + kc];
                afr[mt][1] = As[(rm + 8) * 36 + kc];
                afr[mt][2] = As[rm * 36 + kc + 4];
                afr[mt][3] = As[(rm + 8) * 36 + kc + 4];
            }
#pragma unroll
            for (int nt = 0; nt < 4; nt++) {
                const int rn = wn0 + nt * 8 + (lane >> 2);
                bfr[nt][0] = Bs[rn * 36 + kc];
                bfr[nt][1] = Bs[rn * 36 + kc + 4];
            }
#pragma unroll
            for (int mt = 0; mt < 2; mt++)
#pragma unroll
                for (int nt = 0; nt < 4; nt++)
                    mma_tf32(acc[mt][nt], afr[mt], bfr[nt]);
        }
        __syncthreads();
        if (c + 1 < NC) {
#pragma unroll
            for (int i = 0; i < 4; i++) {
                const uint32_t off = (uint32_t)((lm + i * 32) * 36 + lks * 4) * 4u;
                asm volatile("st.shared.v4.b32 [%0], {%1,%2,%3,%4};" ::
                    "r"(as_base + off), "r"(f2tf32(pa[i].x)), "r"(f2tf32(pa[i].y)),
                    "r"(f2tf32(pa[i].z)), "r"(f2tf32(pa[i].w)) : "memory");
            }
#pragma unroll
            for (int i = 0; i < 2; i++) {
                const int kk = bk + i * 16;
                Bs[(bn4 + 0) * 36 + kk] = f2tf32(pb[i].x);
                Bs[(bn4 + 1) * 36 + kk] = f2tf32(pb[i].y);
                Bs[(bn4 + 2) * 36 + kk] = f2tf32(pb[i].z);
                Bs[(bn4 + 3) * 36 + kk] = f2tf32(pb[i].w);
            }
            __syncthreads();
        }
    }

#pragma unroll
    for (int mt = 0; mt < 2; mt++) {
        const int row = ti + wm0 + mt * 16 + (lane >> 2);
#pragma unroll
        for (int nt = 0; nt < 4; nt++) {
            const int col = wn0 + nt * 8 + 2 * (lane & 3);
#pragma unroll
            for (int half = 0; half < 2; half++) {
                float* cr = out + (size_t)(b * SEQ + row + half * 8) * DMODEL + h * DK + col;
                cr[0] = acc[mt][nt][half * 2 + 0];
                cr[1] = acc[mt][nt][half * 2 + 1];
            }
        }
    }
}

// ---------------------------------------------------------------------------
// Softmax with mask
// ---------------------------------------------------------------------------
__global__ void softmax_kernel(float* __restrict__ scores, const int* __restrict__ mask)
{
    const size_t r = blockIdx.x;
    const int b = (int)(r / ((size_t)NHEAD * SEQ));
    float* row = scores + r * SEQ;
    const int* mrow = mask + (size_t)b * SEQ;
    const int t = threadIdx.x;

    float vals[8];
    float mx = -3.402823e38f;
#pragma unroll
    for (int it = 0; it < 8; it++) {
        const int j = t + it * 256;
        float v = row[j];
        if (mrow[j] == 0) v = -1e9f;
        vals[it] = v;
        mx = fmaxf(mx, v);
    }
    __shared__ float red[32];
    const int lane = t & 31, wid = t >> 5;
#pragma unroll
    for (int o = 16; o > 0; o >>= 1) mx = fmaxf(mx, __shfl_xor_sync(0xffffffffu, mx, o));
    if (lane == 0) red[wid] = mx;
    __syncthreads();
    if (wid == 0) {
        mx = (lane < 8) ? red[lane] : -3.402823e38f;
#pragma unroll
        for (int o = 4; o > 0; o >>= 1) mx = fmaxf(mx, __shfl_xor_sync(0xffffffffu, mx, o));
        if (lane == 0) red[0] = mx;
    }
    __syncthreads();
    mx = red[0];

    float sum = 0.f;
#pragma unroll
    for (int it = 0; it < 8; it++) {
        const float e = __expf(vals[it] - mx);
        vals[it] = e;
        sum += e;
    }
    __syncthreads();
#pragma unroll
    for (int o = 16; o > 0; o >>= 1) sum += __shfl_xor_sync(0xffffffffu, sum, o);
    if (lane == 0) red[wid] = sum;
    __syncthreads();
    if (wid == 0) {
        sum = (lane < 8) ? red[lane] : 0.f;
#pragma unroll
        for (int o = 4; o > 0; o >>= 1) sum += __shfl_xor_sync(0xffffffffu, sum, o);
        if (lane == 0) red[0] = sum;
    }
    __syncthreads();
    const float inv = 1.0f / red[0];
#pragma unroll
    for (int it = 0; it < 8; it++) row[t + it * 256] = vals[it] * inv;
}

// ---------------------------------------------------------------------------
// Launch sequence
// ---------------------------------------------------------------------------
extern "C" void kernel_launch(void* const* d_in, const int* in_sizes, int n_in,
                              void* d_out, int out_size)
{
    const float* x    = (const float*)d_in[0];
    const int*   mask = (const int*)  d_in[1];
    const float* wq   = (const float*)d_in[2];
    const float* bq   = (const float*)d_in[3];
    const float* wk   = (const float*)d_in[4];
    const float* bk   = (const float*)d_in[5];
    const float* wv   = (const float*)d_in[6];
    const float* bv   = (const float*)d_in[7];
    const float* wo   = (const float*)d_in[8];
    const float* bo   = (const float*)d_in[9];
    const float* w1   = (const float*)d_in[10];
    const float* b1   = (const float*)d_in[11];
    const float* w2   = (const float*)d_in[12];
    const float* b2   = (const float*)d_in[13];
    const float* a1   = (const float*)d_in[14];
    const float* n1   = (const float*)d_in[15];
    const float* a2   = (const float*)d_in[16];
    const float* n2   = (const float*)d_in[17];
    float* out = (float*)d_out;

    float *xn, *q, *k, *v, *attn, *x1, *ff, *scores;
    cudaGetSymbolAddress((void**)&xn,     g_xn);
    cudaGetSymbolAddress((void**)&q,      g_q);
    cudaGetSymbolAddress((void**)&k,      g_k);
    cudaGetSymbolAddress((void**)&v,      g_v);
    cudaGetSymbolAddress((void**)&attn,   g_attn);
    cudaGetSymbolAddress((void**)&x1,     g_x1);
    cudaGetSymbolAddress((void**)&ff,     g_ff);
    cudaGetSymbolAddress((void**)&scores, g_scores);

    // --- residual 1: pre-norm + attention ---
    ln_kernel<<<MTOK, 256>>>(x, xn, a1, n1);

    dim3 g1024(DMODEL / 128, MTOK / 128);      // (8, 32)
    gemm_mma<0><<<g1024, 256>>>(xn, wq, bq, nullptr, q, MTOK, DMODEL, DMODEL,
                                DMODEL, DMODEL, DMODEL, 1.f, 0, 0, 0);
    gemm_mma<0><<<g1024, 256>>>(xn, wk, bk, nullptr, k, MTOK, DMODEL, DMODEL,
                                DMODEL, DMODEL, DMODEL, 1.f, 0, 0, 0);
    gemm_mma<0><<<g1024, 256>>>(xn, wv, bv, nullptr, v, MTOK, DMODEL, DMODEL,
                                DMODEL, DMODEL, DMODEL, 1.f, 0, 0, 0);

    // scores[bh] = Q_bh @ K_bh^T / 8 ; one launch per batch, z = head
    for (int b = 0; b < BATCH; b++) {
        gemm_mma<3><<<dim3(SEQ / 128, SEQ / 128, NHEAD), 256>>>(
            q + (size_t)b * SEQ * DMODEL, k + (size_t)b * SEQ * DMODEL,
            nullptr, nullptr,
            scores + (size_t)b * NHEAD * SEQ * SEQ,
            SEQ, SEQ, DK, DMODEL, DMODEL, SEQ, 0.125f,
            DK, DK, (size_t)SEQ * SEQ);
    }

    softmax_kernel<<<BATCH * NHEAD * SEQ, 256>>>(scores, mask);

    pv_mma<<<dim3(1, SEQ / 128, BATCH * NHEAD), 256>>>(scores, v, attn);

    gemm_mma<2><<<g1024, 256>>>(attn, wo, bo, x, x1, MTOK, DMODEL, DMODEL,
                                DMODEL, DMODEL, DMODEL, 1.f, 0, 0, 0);

    // --- residual 2: pre-norm + FFN ---
    ln_kernel<<<MTOK, 256>>>(x1, xn, a2, n2);

    dim3 gff1(DFF / 128, MTOK / 128);              // (32, 32)
    gemm_mma<1><<<gff1, 256>>>(xn, w1, b1, nullptr, ff, MTOK, DFF, DMODEL,
                               DMODEL, DMODEL, DFF, 1.f, 0, 0, 0);

    dim3 gff2(DMODEL / 128, MTOK / 128);           // (8, 32)
    gemm_mma<2><<<gff2, 256>>>(ff, w2, b2, x1, out, MTOK, DMODEL, DFF,
                               DFF, DFF, DMODEL, 1.f, 0, 0, 0);
}

// round 5
// speedup vs baseline: 3.0807x; 1.2035x over previous
#include <cuda_runtime.h>
#include <cuda_bf16.h>
#include <math.h>
#include <stdint.h>

// Problem constants
#define BATCH 2
#define SEQ   2048
#define DMODEL 1024
#define NHEAD 16
#define DK    64
#define DFF   4096
#define MTOK  (BATCH * SEQ)           // 4096 tokens
#define LN_EPS 1e-5f

// ---------------- scratch (device globals; no allocation allowed) ----------
__device__ float g_xn  [(size_t)MTOK * DMODEL];
__device__ float g_q   [(size_t)MTOK * DMODEL];
__device__ float g_k   [(size_t)MTOK * DMODEL];
__device__ float g_v   [(size_t)MTOK * DMODEL];
__device__ float g_attn[(size_t)MTOK * DMODEL];
__device__ float g_x1  [(size_t)MTOK * DMODEL];
__device__ float g_ff  [(size_t)MTOK * DFF];

// ============================ helpers ======================================
__device__ __forceinline__ uint32_t smem_u32(const void* p) {
    uint32_t a;
    asm("{ .reg .u64 t; cvta.to.shared.u64 t, %1; cvt.u32.u64 %0, t; }"
        : "=r"(a) : "l"(p));
    return a;
}

__device__ __forceinline__ uint32_t f2tf32(float f) {
    uint32_t r;
    asm("cvt.rna.tf32.f32 %0, %1;" : "=r"(r) : "f"(f));
    return r;
}

__device__ __forceinline__ void mma_tf32(float* c, const uint32_t* a, const uint32_t* b) {
    asm volatile(
        "mma.sync.aligned.m16n8k8.row.col.f32.tf32.tf32.f32 "
        "{%0,%1,%2,%3}, {%4,%5,%6,%7}, {%8,%9}, {%0,%1,%2,%3};"
        : "+f"(c[0]), "+f"(c[1]), "+f"(c[2]), "+f"(c[3])
        : "r"(a[0]), "r"(a[1]), "r"(a[2]), "r"(a[3]),
          "r"(b[0]), "r"(b[1]));
}

// ---------------------------------------------------------------------------
// LayerNorm: one block per row, torch semantics (ddof=1, eps on std).
// ---------------------------------------------------------------------------
__global__ void ln_kernel(const float* __restrict__ x, float* __restrict__ y,
                          const float* __restrict__ alpha, const float* __restrict__ beta)
{
    const size_t r = blockIdx.x;
    const float* xr = x + r * DMODEL;
    float* yr = y + r * DMODEL;
    const int t = threadIdx.x;

    float v[4];
    float s = 0.f, ss = 0.f;
#pragma unroll
    for (int it = 0; it < 4; it++) {
        float a = xr[t + it * 256];
        v[it] = a;
        s += a;
        ss += a * a;
    }
    __shared__ float red[2][32];
    const int lane = t & 31, wid = t >> 5;
#pragma unroll
    for (int o = 16; o > 0; o >>= 1) {
        s  += __shfl_down_sync(0xffffffffu, s,  o);
        ss += __shfl_down_sync(0xffffffffu, ss, o);
    }
    if (lane == 0) { red[0][wid] = s; red[1][wid] = ss; }
    __syncthreads();
    if (wid == 0) {
        s  = (lane < 8) ? red[0][lane] : 0.f;
        ss = (lane < 8) ? red[1][lane] : 0.f;
#pragma unroll
        for (int o = 4; o > 0; o >>= 1) {
            s  += __shfl_down_sync(0xffffffffu, s,  o);
            ss += __shfl_down_sync(0xffffffffu, ss, o);
        }
        if (lane == 0) { red[0][0] = s; red[1][0] = ss; }
    }
    __syncthreads();
    s = red[0][0]; ss = red[1][0];

    const float mean = s * (1.0f / DMODEL);
    float var = (ss - s * mean) * (1.0f / (DMODEL - 1));
    var = fmaxf(var, 0.f);
    const float inv = alpha[0] / (sqrtf(var) + LN_EPS);
    const float b0 = beta[0];
#pragma unroll
    for (int it = 0; it < 4; it++)
        yr[t + it * 256] = (v[it] - mean) * inv + b0;
}

// ---------------------------------------------------------------------------
// Generalized GEMM on mma.sync tf32 (proven in R4):
//   C[M,N](ldc) = op( A[M,K](lda) @ B[N,K](ldb)^T )
// Block tile 128x128, BK=32, 256 threads = 8 warps (2Mx4N), warp 64x32.
// EPI: 0 = +bias, 1 = +bias,relu, 2 = +bias,+residual
// ---------------------------------------------------------------------------
template <int EPI>
__global__ __launch_bounds__(256) void gemm_mma(
    const float* __restrict__ A, const float* __restrict__ B,
    const float* __restrict__ bias, const float* __restrict__ res,
    float* __restrict__ C, int M, int N, int K,
    int lda, int ldb, int ldc)
{
    __shared__ uint32_t As[128 * 36];
    __shared__ uint32_t Bs[128 * 36];

    const int tid = threadIdx.x;
    const int lane = tid & 31, wid = tid >> 5;
    const int bm = blockIdx.y * 128, bn = blockIdx.x * 128;
    const int wm0 = (wid >> 2) * 64;
    const int wn0 = (wid & 3) * 32;

    const uint32_t as_base = smem_u32(As);
    const uint32_t bs_base = smem_u32(Bs);

    const int lm = tid >> 3;
    const int lks = tid & 7;

    float4 pa[4], pb[4];
    const int NC = K >> 5;

#pragma unroll
    for (int i = 0; i < 4; i++) {
        const int m = lm + i * 32;
        pa[i] = *(const float4*)(A + (size_t)(bm + m) * lda + lks * 4);
        pb[i] = *(const float4*)(B + (size_t)(bn + m) * ldb + lks * 4);
    }
#pragma unroll
    for (int i = 0; i < 4; i++) {
        const int m = lm + i * 32;
        const uint32_t off = (uint32_t)(m * 36 + lks * 4) * 4u;
        asm volatile("st.shared.v4.b32 [%0], {%1,%2,%3,%4};" ::
            "r"(as_base + off), "r"(f2tf32(pa[i].x)), "r"(f2tf32(pa[i].y)),
            "r"(f2tf32(pa[i].z)), "r"(f2tf32(pa[i].w)) : "memory");
        asm volatile("st.shared.v4.b32 [%0], {%1,%2,%3,%4};" ::
            "r"(bs_base + off), "r"(f2tf32(pb[i].x)), "r"(f2tf32(pb[i].y)),
            "r"(f2tf32(pb[i].z)), "r"(f2tf32(pb[i].w)) : "memory");
    }
    __syncthreads();

    float acc[4][4][4];
#pragma unroll
    for (int mt = 0; mt < 4; mt++)
#pragma unroll
        for (int nt = 0; nt < 4; nt++)
#pragma unroll
            for (int j = 0; j < 4; j++) acc[mt][nt][j] = 0.f;

    for (int c = 0; c < NC; c++) {
        if (c + 1 < NC) {
#pragma unroll
            for (int i = 0; i < 4; i++) {
                const int m = lm + i * 32;
                pa[i] = *(const float4*)(A + (size_t)(bm + m) * lda + (c + 1) * 32 + lks * 4);
                pb[i] = *(const float4*)(B + (size_t)(bn + m) * ldb + (c + 1) * 32 + lks * 4);
            }
        }
#pragma unroll
        for (int ks = 0; ks < 4; ks++) {
            const int kc = ks * 8 + (lane & 3);
            uint32_t afr[4][4], bfr[4][2];
#pragma unroll
            for (int mt = 0; mt < 4; mt++) {
                const int rm = wm0 + mt * 16 + (lane >> 2);
                afr[mt][0] = As[rm * 36 + kc];
                afr[mt][1] = As[(rm + 8) * 36 + kc];
                afr[mt][2] = As[rm * 36 + kc + 4];
                afr[mt][3] = As[(rm + 8) * 36 + kc + 4];
            }
#pragma unroll
            for (int nt = 0; nt < 4; nt++) {
                const int rn = wn0 + nt * 8 + (lane >> 2);
                bfr[nt][0] = Bs[rn * 36 + kc];
                bfr[nt][1] = Bs[rn * 36 + kc + 4];
            }
#pragma unroll
            for (int mt = 0; mt < 4; mt++)
#pragma unroll
                for (int nt = 0; nt < 4; nt++)
                    mma_tf32(acc[mt][nt], afr[mt], bfr[nt]);
        }
        __syncthreads();
        if (c + 1 < NC) {
#pragma unroll
            for (int i = 0; i < 4; i++) {
                const int m = lm + i * 32;
                const uint32_t off = (uint32_t)(m * 36 + lks * 4) * 4u;
                asm volatile("st.shared.v4.b32 [%0], {%1,%2,%3,%4};" ::
                    "r"(as_base + off), "r"(f2tf32(pa[i].x)), "r"(f2tf32(pa[i].y)),
                    "r"(f2tf32(pa[i].z)), "r"(f2tf32(pa[i].w)) : "memory");
                asm volatile("st.shared.v4.b32 [%0], {%1,%2,%3,%4};" ::
                    "r"(bs_base + off), "r"(f2tf32(pb[i].x)), "r"(f2tf32(pb[i].y)),
                    "r"(f2tf32(pb[i].z)), "r"(f2tf32(pb[i].w)) : "memory");
            }
            __syncthreads();
        }
    }

#pragma unroll
    for (int mt = 0; mt < 4; mt++) {
        const int row = bm + wm0 + mt * 16 + (lane >> 2);
#pragma unroll
        for (int nt = 0; nt < 4; nt++) {
            const int col = bn + wn0 + nt * 8 + 2 * (lane & 3);
            const float b0 = bias[col], b1 = bias[col + 1];
#pragma unroll
            for (int half = 0; half < 2; half++) {
                const int r = row + half * 8;
                float v0 = acc[mt][nt][half * 2 + 0] + b0;
                float v1 = acc[mt][nt][half * 2 + 1] + b1;
                if (EPI == 1) { v0 = fmaxf(v0, 0.f); v1 = fmaxf(v1, 0.f); }
                if (EPI == 2) {
                    const float* rr = res + (size_t)r * ldc + col;
                    v0 += rr[0]; v1 += rr[1];
                }
                float* cr = C + (size_t)r * ldc + col;
                cr[0] = v0; cr[1] = v1;
            }
        }
    }
}

// ---------------------------------------------------------------------------
// Flash attention: fused scores + mask + softmax + PV, one head per CTA-y.
// BQ=64 queries per CTA, 128 threads = 4 warps, each warp owns 16 q-rows.
// K/V tiles of 64 rows streamed through SMEM; online softmax in registers;
// P staged per-warp in SMEM (warp-private rows -> syncwarp only).
// All MMAs tf32. Q pre-scaled by 1/sqrt(DK)=0.125 at load.
// ---------------------------------------------------------------------------
#define BQ  64
#define BKV 64
#define FPAD 68
#define FLASH_SMEM ((4 * BQ * FPAD) * 4 + BKV * 4)

__global__ __launch_bounds__(128) void flash_attn(
    const float* __restrict__ q, const float* __restrict__ kbuf,
    const float* __restrict__ vbuf, const int* __restrict__ mask,
    float* __restrict__ out)
{
    extern __shared__ uint32_t fsm[];
    uint32_t* Qs = fsm;                 // [BQ][FPAD]   (tf32, pre-scaled)
    uint32_t* Ks = Qs + BQ * FPAD;      // [BKV][FPAD]  ([j][d], tf32)
    uint32_t* Vs = Ks + BKV * FPAD;     // [BKV][FPAD]  ([j][d], tf32)
    uint32_t* Ps = Vs + BKV * FPAD;     // [BQ][FPAD]   (tf32 probs)
    int* msk = (int*)(Ps + BQ * FPAD);  // [BKV]

    const int bh = blockIdx.y;
    const int b = bh / NHEAD, h = bh % NHEAD;
    const int qi0 = blockIdx.x * BQ;
    const float* Qg = q    + ((size_t)(b * SEQ + qi0)) * DMODEL + h * DK;
    const float* Kg = kbuf + ((size_t)b * SEQ) * DMODEL + h * DK;
    const float* Vg = vbuf + ((size_t)b * SEQ) * DMODEL + h * DK;

    const int tid = threadIdx.x;
    const int lane = tid & 31, wid = tid >> 5;
    const int g = lane >> 2, t = lane & 3;
    const int ar = wid * 16 + g;         // this lane's base q-row in tile
    const int c2 = 2 * t;

    // ---- load Q tile (scaled) ----
#pragma unroll
    for (int i = 0; i < 8; i++) {
        const int idx = tid + i * 128;
        const int row = idx >> 4, c4 = idx & 15;
        float4 qv = *(const float4*)(Qg + (size_t)row * DMODEL + c4 * 4);
        uint32_t* dst = Qs + row * FPAD + c4 * 4;
        dst[0] = f2tf32(qv.x * 0.125f);
        dst[1] = f2tf32(qv.y * 0.125f);
        dst[2] = f2tf32(qv.z * 0.125f);
        dst[3] = f2tf32(qv.w * 0.125f);
    }

    float m0 = -INFINITY, m1 = -INFINITY, l0 = 0.f, l1 = 0.f;
    float o[8][4];
#pragma unroll
    for (int nt = 0; nt < 8; nt++)
#pragma unroll
        for (int j = 0; j < 4; j++) o[nt][j] = 0.f;

    for (int jt = 0; jt < SEQ; jt += BKV) {
        // ---- load K/V tiles + mask ----
#pragma unroll
        for (int i = 0; i < 8; i++) {
            const int idx = tid + i * 128;
            const int row = idx >> 4, c4 = idx & 15;
            float4 kv = *(const float4*)(Kg + (size_t)(jt + row) * DMODEL + c4 * 4);
            float4 vv = *(const float4*)(Vg + (size_t)(jt + row) * DMODEL + c4 * 4);
            uint32_t* kd = Ks + row * FPAD + c4 * 4;
            kd[0] = f2tf32(kv.x); kd[1] = f2tf32(kv.y);
            kd[2] = f2tf32(kv.z); kd[3] = f2tf32(kv.w);
            uint32_t* vd = Vs + row * FPAD + c4 * 4;
            vd[0] = f2tf32(vv.x); vd[1] = f2tf32(vv.y);
            vd[2] = f2tf32(vv.z); vd[3] = f2tf32(vv.w);
        }
        if (tid < BKV) msk[tid] = mask[(size_t)b * SEQ + jt + tid];
        __syncthreads();

        // ---- S = Q @ K^T (already scaled) ----
        float s[8][4];
#pragma unroll
        for (int nt = 0; nt < 8; nt++)
#pragma unroll
            for (int j = 0; j < 4; j++) s[nt][j] = 0.f;

#pragma unroll
        for (int ks = 0; ks < 8; ks++) {
            const int kc = ks * 8 + t;
            uint32_t a[4];
            a[0] = Qs[ar * FPAD + kc];
            a[1] = Qs[(ar + 8) * FPAD + kc];
            a[2] = Qs[ar * FPAD + kc + 4];
            a[3] = Qs[(ar + 8) * FPAD + kc + 4];
#pragma unroll
            for (int nt = 0; nt < 8; nt++) {
                const int rn = nt * 8 + g;
                uint32_t bb[2] = { Ks[rn * FPAD + kc], Ks[rn * FPAD + kc + 4] };
                mma_tf32(s[nt], a, bb);
            }
        }

        // ---- mask ----
#pragma unroll
        for (int nt = 0; nt < 8; nt++) {
            const int c0 = nt * 8 + c2;
            if (msk[c0] == 0)     { s[nt][0] = -1e9f; s[nt][2] = -1e9f; }
            if (msk[c0 + 1] == 0) { s[nt][1] = -1e9f; s[nt][3] = -1e9f; }
        }

        // ---- online softmax ----
        float mx0 = -INFINITY, mx1 = -INFINITY;
#pragma unroll
        for (int nt = 0; nt < 8; nt++) {
            mx0 = fmaxf(mx0, fmaxf(s[nt][0], s[nt][1]));
            mx1 = fmaxf(mx1, fmaxf(s[nt][2], s[nt][3]));
        }
        mx0 = fmaxf(mx0, __shfl_xor_sync(0xffffffffu, mx0, 1));
        mx0 = fmaxf(mx0, __shfl_xor_sync(0xffffffffu, mx0, 2));
        mx1 = fmaxf(mx1, __shfl_xor_sync(0xffffffffu, mx1, 1));
        mx1 = fmaxf(mx1, __shfl_xor_sync(0xffffffffu, mx1, 2));

        const float mn0 = fmaxf(m0, mx0), mn1 = fmaxf(m1, mx1);
        const float sc0 = __expf(m0 - mn0), sc1 = __expf(m1 - mn1);

        float sum0 = 0.f, sum1 = 0.f;
#pragma unroll
        for (int nt = 0; nt < 8; nt++) {
            const float p0 = __expf(s[nt][0] - mn0);
            const float p1 = __expf(s[nt][1] - mn0);
            const float p2 = __expf(s[nt][2] - mn1);
            const float p3 = __expf(s[nt][3] - mn1);
            sum0 += p0 + p1; sum1 += p2 + p3;
            const int c0 = nt * 8 + c2;
            Ps[ar * FPAD + c0]           = f2tf32(p0);
            Ps[ar * FPAD + c0 + 1]       = f2tf32(p1);
            Ps[(ar + 8) * FPAD + c0]     = f2tf32(p2);
            Ps[(ar + 8) * FPAD + c0 + 1] = f2tf32(p3);
            o[nt][0] *= sc0; o[nt][1] *= sc0;
            o[nt][2] *= sc1; o[nt][3] *= sc1;
        }
        sum0 += __shfl_xor_sync(0xffffffffu, sum0, 1);
        sum0 += __shfl_xor_sync(0xffffffffu, sum0, 2);
        sum1 += __shfl_xor_sync(0xffffffffu, sum1, 1);
        sum1 += __shfl_xor_sync(0xffffffffu, sum1, 2);
        l0 = l0 * sc0 + sum0;
        l1 = l1 * sc1 + sum1;
        m0 = mn0; m1 = mn1;
        __syncwarp();     // Ps rows are warp-private; warp-level sync suffices

        // ---- O += P @ V ----
#pragma unroll
        for (int ks = 0; ks < 8; ks++) {
            const int kc = ks * 8 + t;     // j index within tile
            uint32_t a[4];
            a[0] = Ps[ar * FPAD + kc];
            a[1] = Ps[(ar + 8) * FPAD + kc];
            a[2] = Ps[ar * FPAD + kc + 4];
            a[3] = Ps[(ar + 8) * FPAD + kc + 4];
#pragma unroll
            for (int nt = 0; nt < 8; nt++) {
                const int rn = nt * 8 + g;  // d index
                uint32_t bb[2] = { Vs[kc * FPAD + rn], Vs[(kc + 4) * FPAD + rn] };
                mma_tf32(o[nt], a, bb);
            }
        }
        __syncthreads();   // all warps done with Ks/Vs before next overwrite
    }

    // ---- epilogue: normalize + write ----
    const float inv0 = 1.f / l0, inv1 = 1.f / l1;
    float* Og = out + ((size_t)(b * SEQ + qi0)) * DMODEL + h * DK;
#pragma unroll
    for (int nt = 0; nt < 8; nt++) {
        const int c0 = nt * 8 + c2;
        Og[(size_t)ar * DMODEL + c0]           = o[nt][0] * inv0;
        Og[(size_t)ar * DMODEL + c0 + 1]       = o[nt][1] * inv0;
        Og[(size_t)(ar + 8) * DMODEL + c0]     = o[nt][2] * inv1;
        Og[(size_t)(ar + 8) * DMODEL + c0 + 1] = o[nt][3] * inv1;
    }
}

// ---------------------------------------------------------------------------
// Launch sequence
// ---------------------------------------------------------------------------
extern "C" void kernel_launch(void* const* d_in, const int* in_sizes, int n_in,
                              void* d_out, int out_size)
{
    const float* x    = (const float*)d_in[0];
    const int*   mask = (const int*)  d_in[1];
    const float* wq   = (const float*)d_in[2];
    const float* bq   = (const float*)d_in[3];
    const float* wk   = (const float*)d_in[4];
    const float* bk   = (const float*)d_in[5];
    const float* wv   = (const float*)d_in[6];
    const float* bv   = (const float*)d_in[7];
    const float* wo   = (const float*)d_in[8];
    const float* bo   = (const float*)d_in[9];
    const float* w1   = (const float*)d_in[10];
    const float* b1   = (const float*)d_in[11];
    const float* w2   = (const float*)d_in[12];
    const float* b2   = (const float*)d_in[13];
    const float* a1   = (const float*)d_in[14];
    const float* n1   = (const float*)d_in[15];
    const float* a2   = (const float*)d_in[16];
    const float* n2   = (const float*)d_in[17];
    float* out = (float*)d_out;

    float *xn, *q, *k, *v, *attn, *x1, *ff;
    cudaGetSymbolAddress((void**)&xn,   g_xn);
    cudaGetSymbolAddress((void**)&q,    g_q);
    cudaGetSymbolAddress((void**)&k,    g_k);
    cudaGetSymbolAddress((void**)&v,    g_v);
    cudaGetSymbolAddress((void**)&attn, g_attn);
    cudaGetSymbolAddress((void**)&x1,   g_x1);
    cudaGetSymbolAddress((void**)&ff,   g_ff);

    cudaFuncSetAttribute(flash_attn,
                         cudaFuncAttributeMaxDynamicSharedMemorySize, FLASH_SMEM);

    // --- residual 1: pre-norm + attention ---
    ln_kernel<<<MTOK, 256>>>(x, xn, a1, n1);

    dim3 g1024(DMODEL / 128, MTOK / 128);      // (8, 32)
    gemm_mma<0><<<g1024, 256>>>(xn, wq, bq, nullptr, q, MTOK, DMODEL, DMODEL,
                                DMODEL, DMODEL, DMODEL);
    gemm_mma<0><<<g1024, 256>>>(xn, wk, bk, nullptr, k, MTOK, DMODEL, DMODEL,
                                DMODEL, DMODEL, DMODEL);
    gemm_mma<0><<<g1024, 256>>>(xn, wv, bv, nullptr, v, MTOK, DMODEL, DMODEL,
                                DMODEL, DMODEL, DMODEL);

    flash_attn<<<dim3(SEQ / BQ, BATCH * NHEAD), 128, FLASH_SMEM>>>(
        q, k, v, mask, attn);

    gemm_mma<2><<<g1024, 256>>>(attn, wo, bo, x, x1, MTOK, DMODEL, DMODEL,
                                DMODEL, DMODEL, DMODEL);

    // --- residual 2: pre-norm + FFN ---
    ln_kernel<<<MTOK, 256>>>(x1, xn, a2, n2);

    dim3 gff1(DFF / 128, MTOK / 128);              // (32, 32)
    gemm_mma<1><<<gff1, 256>>>(xn, w1, b1, nullptr, ff, MTOK, DFF, DMODEL,
                               DMODEL, DMODEL, DFF);

    dim3 gff2(DMODEL / 128, MTOK / 128);           // (8, 32)
    gemm_mma<2><<<gff2, 256>>>(ff, w2, b2, x1, out, MTOK, DMODEL, DFF,
                               DFF, DFF, DMODEL);
}

// round 6
// speedup vs baseline: 3.3164x; 1.0765x over previous
#include <cuda_runtime.h>
#include <cuda_bf16.h>
#include <math.h>
#include <stdint.h>

// Problem constants
#define BATCH 2
#define SEQ   2048
#define DMODEL 1024
#define NHEAD 16
#define DK    64
#define DFF   4096
#define MTOK  (BATCH * SEQ)           // 4096 tokens
#define LN_EPS 1e-5f

// ---------------- scratch (device globals; no allocation allowed) ----------
__device__ float g_xn  [(size_t)MTOK * DMODEL];
__device__ float g_q   [(size_t)MTOK * DMODEL];
__device__ float g_k   [(size_t)MTOK * DMODEL];
__device__ float g_v   [(size_t)MTOK * DMODEL];
__device__ float g_attn[(size_t)MTOK * DMODEL];
__device__ float g_x1  [(size_t)MTOK * DMODEL];
__device__ float g_ff  [(size_t)MTOK * DFF];

// ============================ helpers ======================================
__device__ __forceinline__ uint32_t smem_u32(const void* p) {
    uint32_t a;
    asm("{ .reg .u64 t; cvta.to.shared.u64 t, %1; cvt.u32.u64 %0, t; }"
        : "=r"(a) : "l"(p));
    return a;
}

__device__ __forceinline__ uint32_t f2tf32(float f) {
    uint32_t r;
    asm("cvt.rna.tf32.f32 %0, %1;" : "=r"(r) : "f"(f));
    return r;
}

__device__ __forceinline__ void mma_tf32(float* c, const uint32_t* a, const uint32_t* b) {
    asm volatile(
        "mma.sync.aligned.m16n8k8.row.col.f32.tf32.tf32.f32 "
        "{%0,%1,%2,%3}, {%4,%5,%6,%7}, {%8,%9}, {%0,%1,%2,%3};"
        : "+f"(c[0]), "+f"(c[1]), "+f"(c[2]), "+f"(c[3])
        : "r"(a[0]), "r"(a[1]), "r"(a[2]), "r"(a[3]),
          "r"(b[0]), "r"(b[1]));
}

#define CP_ASYNC16(dst, src) \
    asm volatile("cp.async.cg.shared.global [%0], [%1], 16;" :: \
        "r"(dst), "l"(src) : "memory")
#define CP_COMMIT() asm volatile("cp.async.commit_group;" ::: "memory")
#define CP_WAIT(n)  asm volatile("cp.async.wait_group %0;" :: "n"(n) : "memory")

// ---------------------------------------------------------------------------
// LayerNorm: one block per row, torch semantics (ddof=1, eps on std).
// ---------------------------------------------------------------------------
__global__ void ln_kernel(const float* __restrict__ x, float* __restrict__ y,
                          const float* __restrict__ alpha, const float* __restrict__ beta)
{
    const size_t r = blockIdx.x;
    const float* xr = x + r * DMODEL;
    float* yr = y + r * DMODEL;
    const int t = threadIdx.x;

    float v[4];
    float s = 0.f, ss = 0.f;
#pragma unroll
    for (int it = 0; it < 4; it++) {
        float a = xr[t + it * 256];
        v[it] = a;
        s += a;
        ss += a * a;
    }
    __shared__ float red[2][32];
    const int lane = t & 31, wid = t >> 5;
#pragma unroll
    for (int o = 16; o > 0; o >>= 1) {
        s  += __shfl_down_sync(0xffffffffu, s,  o);
        ss += __shfl_down_sync(0xffffffffu, ss, o);
    }
    if (lane == 0) { red[0][wid] = s; red[1][wid] = ss; }
    __syncthreads();
    if (wid == 0) {
        s  = (lane < 8) ? red[0][lane] : 0.f;
        ss = (lane < 8) ? red[1][lane] : 0.f;
#pragma unroll
        for (int o = 4; o > 0; o >>= 1) {
            s  += __shfl_down_sync(0xffffffffu, s,  o);
            ss += __shfl_down_sync(0xffffffffu, ss, o);
        }
        if (lane == 0) { red[0][0] = s; red[1][0] = ss; }
    }
    __syncthreads();
    s = red[0][0]; ss = red[1][0];

    const float mean = s * (1.0f / DMODEL);
    float var = (ss - s * mean) * (1.0f / (DMODEL - 1));
    var = fmaxf(var, 0.f);
    const float inv = alpha[0] / (sqrtf(var) + LN_EPS);
    const float b0 = beta[0];
#pragma unroll
    for (int it = 0; it < 4; it++)
        yr[t + it * 256] = (v[it] - mean) * inv + b0;
}

// ---------------------------------------------------------------------------
// Dense GEMM, mma.sync tf32 with cp.async double-buffer:
//   C[M,N](ldc) = op( A[M,K](lda) @ B[N,K](ldb)^T )
// 128x128 tile, BK=32, 256 threads = 8 warps (2Mx4N), warp 64x32, 2 CTAs/SM.
// Inputs land as raw fp32; tf32 MMA truncates mantissa in-hardware.
// EPI: 0 = +bias, 1 = +bias,relu, 2 = +bias,+residual
// ---------------------------------------------------------------------------
#define GPAD 36
#define GEMM_SMEM (4 * 128 * GPAD * 4)

template <int EPI>
__global__ __launch_bounds__(256, 2) void gemm_mma(
    const float* __restrict__ A, const float* __restrict__ B,
    const float* __restrict__ bias, const float* __restrict__ res,
    float* __restrict__ C, int M, int N, int K,
    int lda, int ldb, int ldc)
{
    extern __shared__ uint32_t gsm[];
    uint32_t* AS[2] = { gsm,                gsm + 128 * GPAD };
    uint32_t* BS[2] = { gsm + 2 * 128 * GPAD, gsm + 3 * 128 * GPAD };

    const int tid = threadIdx.x;
    const int lane = tid & 31, wid = tid >> 5;
    const int bm = blockIdx.y * 128, bn = blockIdx.x * 128;
    const int wm0 = (wid >> 2) * 64;
    const int wn0 = (wid & 3) * 32;
    const int lm = tid >> 3;              // loader row class (0..31)
    const int lks = tid & 7;              // 16B slot within 32-float chunk

    const uint32_t as_addr[2] = { smem_u32(AS[0]), smem_u32(AS[1]) };
    const uint32_t bs_addr[2] = { smem_u32(BS[0]), smem_u32(BS[1]) };

    const int NC = K >> 5;

    // ---- issue chunk 0 into stage 0 ----
#pragma unroll
    for (int i = 0; i < 4; i++) {
        const int m = lm + i * 32;
        const uint32_t off = (uint32_t)(m * GPAD + lks * 4) * 4u;
        CP_ASYNC16(as_addr[0] + off, A + (size_t)(bm + m) * lda + lks * 4);
        CP_ASYNC16(bs_addr[0] + off, B + (size_t)(bn + m) * ldb + lks * 4);
    }
    CP_COMMIT();

    float acc[4][4][4];
#pragma unroll
    for (int mt = 0; mt < 4; mt++)
#pragma unroll
        for (int nt = 0; nt < 4; nt++)
#pragma unroll
            for (int j = 0; j < 4; j++) acc[mt][nt][j] = 0.f;

    for (int c = 0; c < NC; c++) {
        const int s = c & 1;
        if (c + 1 < NC) {
            const int s1 = s ^ 1;
#pragma unroll
            for (int i = 0; i < 4; i++) {
                const int m = lm + i * 32;
                const uint32_t off = (uint32_t)(m * GPAD + lks * 4) * 4u;
                CP_ASYNC16(as_addr[s1] + off,
                           A + (size_t)(bm + m) * lda + (c + 1) * 32 + lks * 4);
                CP_ASYNC16(bs_addr[s1] + off,
                           B + (size_t)(bn + m) * ldb + (c + 1) * 32 + lks * 4);
            }
            CP_COMMIT();
            CP_WAIT(1);          // chunk c resident; c+1 may be in flight
        } else {
            CP_WAIT(0);
        }
        __syncthreads();

        const uint32_t* Asb = AS[s];
        const uint32_t* Bsb = BS[s];
#pragma unroll
        for (int ks = 0; ks < 4; ks++) {
            const int kc = ks * 8 + (lane & 3);
            uint32_t afr[4][4], bfr[4][2];
#pragma unroll
            for (int mt = 0; mt < 4; mt++) {
                const int rm = wm0 + mt * 16 + (lane >> 2);
                afr[mt][0] = Asb[rm * GPAD + kc];
                afr[mt][1] = Asb[(rm + 8) * GPAD + kc];
                afr[mt][2] = Asb[rm * GPAD + kc + 4];
                afr[mt][3] = Asb[(rm + 8) * GPAD + kc + 4];
            }
#pragma unroll
            for (int nt = 0; nt < 4; nt++) {
                const int rn = wn0 + nt * 8 + (lane >> 2);
                bfr[nt][0] = Bsb[rn * GPAD + kc];
                bfr[nt][1] = Bsb[rn * GPAD + kc + 4];
            }
#pragma unroll
            for (int mt = 0; mt < 4; mt++)
#pragma unroll
                for (int nt = 0; nt < 4; nt++)
                    mma_tf32(acc[mt][nt], afr[mt], bfr[nt]);
        }
        __syncthreads();          // stage s free for reload at c+2
    }

#pragma unroll
    for (int mt = 0; mt < 4; mt++) {
        const int row = bm + wm0 + mt * 16 + (lane >> 2);
#pragma unroll
        for (int nt = 0; nt < 4; nt++) {
            const int col = bn + wn0 + nt * 8 + 2 * (lane & 3);
            const float b0 = bias[col], b1 = bias[col + 1];
#pragma unroll
            for (int half = 0; half < 2; half++) {
                const int r = row + half * 8;
                float v0 = acc[mt][nt][half * 2 + 0] + b0;
                float v1 = acc[mt][nt][half * 2 + 1] + b1;
                if (EPI == 1) { v0 = fmaxf(v0, 0.f); v1 = fmaxf(v1, 0.f); }
                if (EPI == 2) {
                    const float* rr = res + (size_t)r * ldc + col;
                    v0 += rr[0]; v1 += rr[1];
                }
                float* cr = C + (size_t)r * ldc + col;
                cr[0] = v0; cr[1] = v1;
            }
        }
    }
}

// ---------------------------------------------------------------------------
// Flash attention (unchanged from R5): fused scores+mask+softmax+PV.
// BQ=64 queries per CTA, 128 threads = 4 warps; K/V tiles of 64 streamed.
// ---------------------------------------------------------------------------
#define BQ  64
#define BKV 64
#define FPAD 68
#define FLASH_SMEM ((4 * BQ * FPAD) * 4 + BKV * 4)

__global__ __launch_bounds__(128) void flash_attn(
    const float* __restrict__ q, const float* __restrict__ kbuf,
    const float* __restrict__ vbuf, const int* __restrict__ mask,
    float* __restrict__ out)
{
    extern __shared__ uint32_t fsm[];
    uint32_t* Qs = fsm;
    uint32_t* Ks = Qs + BQ * FPAD;
    uint32_t* Vs = Ks + BKV * FPAD;
    uint32_t* Ps = Vs + BKV * FPAD;
    int* msk = (int*)(Ps + BQ * FPAD);

    const int bh = blockIdx.y;
    const int b = bh / NHEAD, h = bh % NHEAD;
    const int qi0 = blockIdx.x * BQ;
    const float* Qg = q    + ((size_t)(b * SEQ + qi0)) * DMODEL + h * DK;
    const float* Kg = kbuf + ((size_t)b * SEQ) * DMODEL + h * DK;
    const float* Vg = vbuf + ((size_t)b * SEQ) * DMODEL + h * DK;

    const int tid = threadIdx.x;
    const int lane = tid & 31, wid = tid >> 5;
    const int g = lane >> 2, t = lane & 3;
    const int ar = wid * 16 + g;
    const int c2 = 2 * t;

#pragma unroll
    for (int i = 0; i < 8; i++) {
        const int idx = tid + i * 128;
        const int row = idx >> 4, c4 = idx & 15;
        float4 qv = *(const float4*)(Qg + (size_t)row * DMODEL + c4 * 4);
        uint32_t* dst = Qs + row * FPAD + c4 * 4;
        dst[0] = f2tf32(qv.x * 0.125f);
        dst[1] = f2tf32(qv.y * 0.125f);
        dst[2] = f2tf32(qv.z * 0.125f);
        dst[3] = f2tf32(qv.w * 0.125f);
    }

    float m0 = -INFINITY, m1 = -INFINITY, l0 = 0.f, l1 = 0.f;
    float o[8][4];
#pragma unroll
    for (int nt = 0; nt < 8; nt++)
#pragma unroll
        for (int j = 0; j < 4; j++) o[nt][j] = 0.f;

    for (int jt = 0; jt < SEQ; jt += BKV) {
#pragma unroll
        for (int i = 0; i < 8; i++) {
            const int idx = tid + i * 128;
            const int row = idx >> 4, c4 = idx & 15;
            float4 kv = *(const float4*)(Kg + (size_t)(jt + row) * DMODEL + c4 * 4);
            float4 vv = *(const float4*)(Vg + (size_t)(jt + row) * DMODEL + c4 * 4);
            uint32_t* kd = Ks + row * FPAD + c4 * 4;
            kd[0] = f2tf32(kv.x); kd[1] = f2tf32(kv.y);
            kd[2] = f2tf32(kv.z); kd[3] = f2tf32(kv.w);
            uint32_t* vd = Vs + row * FPAD + c4 * 4;
            vd[0] = f2tf32(vv.x); vd[1] = f2tf32(vv.y);
            vd[2] = f2tf32(vv.z); vd[3] = f2tf32(vv.w);
        }
        if (tid < BKV) msk[tid] = mask[(size_t)b * SEQ + jt + tid];
        __syncthreads();

        float s[8][4];
#pragma unroll
        for (int nt = 0; nt < 8; nt++)
#pragma unroll
            for (int j = 0; j < 4; j++) s[nt][j] = 0.f;

#pragma unroll
        for (int ks = 0; ks < 8; ks++) {
            const int kc = ks * 8 + t;
            uint32_t a[4];
            a[0] = Qs[ar * FPAD + kc];
            a[1] = Qs[(ar + 8) * FPAD + kc];
            a[2] = Qs[ar * FPAD + kc + 4];
            a[3] = Qs[(ar + 8) * FPAD + kc + 4];
#pragma unroll
            for (int nt = 0; nt < 8; nt++) {
                const int rn = nt * 8 + g;
                uint32_t bb[2] = { Ks[rn * FPAD + kc], Ks[rn * FPAD + kc + 4] };
                mma_tf32(s[nt], a, bb);
            }
        }

#pragma unroll
        for (int nt = 0; nt < 8; nt++) {
            const int c0 = nt * 8 + c2;
            if (msk[c0] == 0)     { s[nt][0] = -1e9f; s[nt][2] = -1e9f; }
            if (msk[c0 + 1] == 0) { s[nt][1] = -1e9f; s[nt][3] = -1e9f; }
        }

        float mx0 = -INFINITY, mx1 = -INFINITY;
#pragma unroll
        for (int nt = 0; nt < 8; nt++) {
            mx0 = fmaxf(mx0, fmaxf(s[nt][0], s[nt][1]));
            mx1 = fmaxf(mx1, fmaxf(s[nt][2], s[nt][3]));
        }
        mx0 = fmaxf(mx0, __shfl_xor_sync(0xffffffffu, mx0, 1));
        mx0 = fmaxf(mx0, __shfl_xor_sync(0xffffffffu, mx0, 2));
        mx1 = fmaxf(mx1, __shfl_xor_sync(0xffffffffu, mx1, 1));
        mx1 = fmaxf(mx1, __shfl_xor_sync(0xffffffffu, mx1, 2));

        const float mn0 = fmaxf(m0, mx0), mn1 = fmaxf(m1, mx1);
        const float sc0 = __expf(m0 - mn0), sc1 = __expf(m1 - mn1);

        float sum0 = 0.f, sum1 = 0.f;
#pragma unroll
        for (int nt = 0; nt < 8; nt++) {
            const float p0 = __expf(s[nt][0] - mn0);
            const float p1 = __expf(s[nt][1] - mn0);
            const float p2 = __expf(s[nt][2] - mn1);
            const float p3 = __expf(s[nt][3] - mn1);
            sum0 += p0 + p1; sum1 += p2 + p3;
            const int c0 = nt * 8 + c2;
            Ps[ar * FPAD + c0]           = f2tf32(p0);
            Ps[ar * FPAD + c0 + 1]       = f2tf32(p1);
            Ps[(ar + 8) * FPAD + c0]     = f2tf32(p2);
            Ps[(ar + 8) * FPAD + c0 + 1] = f2tf32(p3);
            o[nt][0] *= sc0; o[nt][1] *= sc0;
            o[nt][2] *= sc1; o[nt][3] *= sc1;
        }
        sum0 += __shfl_xor_sync(0xffffffffu, sum0, 1);
        sum0 += __shfl_xor_sync(0xffffffffu, sum0, 2);
        sum1 += __shfl_xor_sync(0xffffffffu, sum1, 1);
        sum1 += __shfl_xor_sync(0xffffffffu, sum1, 2);
        l0 = l0 * sc0 + sum0;
        l1 = l1 * sc1 + sum1;
        m0 = mn0; m1 = mn1;
        __syncwarp();

#pragma unroll
        for (int ks = 0; ks < 8; ks++) {
            const int kc = ks * 8 + t;
            uint32_t a[4];
            a[0] = Ps[ar * FPAD + kc];
            a[1] = Ps[(ar + 8) * FPAD + kc];
            a[2] = Ps[ar * FPAD + kc + 4];
            a[3] = Ps[(ar + 8) * FPAD + kc + 4];
#pragma unroll
            for (int nt = 0; nt < 8; nt++) {
                const int rn = nt * 8 + g;
                uint32_t bb[2] = { Vs[kc * FPAD + rn], Vs[(kc + 4) * FPAD + rn] };
                mma_tf32(o[nt], a, bb);
            }
        }
        __syncthreads();
    }

    const float inv0 = 1.f / l0, inv1 = 1.f / l1;
    float* Og = out + ((size_t)(b * SEQ + qi0)) * DMODEL + h * DK;
#pragma unroll
    for (int nt = 0; nt < 8; nt++) {
        const int c0 = nt * 8 + c2;
        Og[(size_t)ar * DMODEL + c0]           = o[nt][0] * inv0;
        Og[(size_t)ar * DMODEL + c0 + 1]       = o[nt][1] * inv0;
        Og[(size_t)(ar + 8) * DMODEL + c0]     = o[nt][2] * inv1;
        Og[(size_t)(ar + 8) * DMODEL + c0 + 1] = o[nt][3] * inv1;
    }
}

// ---------------------------------------------------------------------------
// Launch sequence
// ---------------------------------------------------------------------------
extern "C" void kernel_launch(void* const* d_in, const int* in_sizes, int n_in,
                              void* d_out, int out_size)
{
    const float* x    = (const float*)d_in[0];
    const int*   mask = (const int*)  d_in[1];
    const float* wq   = (const float*)d_in[2];
    const float* bq   = (const float*)d_in[3];
    const float* wk   = (const float*)d_in[4];
    const float* bk   = (const float*)d_in[5];
    const float* wv   = (const float*)d_in[6];
    const float* bv   = (const float*)d_in[7];
    const float* wo   = (const float*)d_in[8];
    const float* bo   = (const float*)d_in[9];
    const float* w1   = (const float*)d_in[10];
    const float* b1   = (const float*)d_in[11];
    const float* w2   = (const float*)d_in[12];
    const float* b2   = (const float*)d_in[13];
    const float* a1   = (const float*)d_in[14];
    const float* n1   = (const float*)d_in[15];
    const float* a2   = (const float*)d_in[16];
    const float* n2   = (const float*)d_in[17];
    float* out = (float*)d_out;

    float *xn, *q, *k, *v, *attn, *x1, *ff;
    cudaGetSymbolAddress((void**)&xn,   g_xn);
    cudaGetSymbolAddress((void**)&q,    g_q);
    cudaGetSymbolAddress((void**)&k,    g_k);
    cudaGetSymbolAddress((void**)&v,    g_v);
    cudaGetSymbolAddress((void**)&attn, g_attn);
    cudaGetSymbolAddress((void**)&x1,   g_x1);
    cudaGetSymbolAddress((void**)&ff,   g_ff);

    cudaFuncSetAttribute(gemm_mma<0>, cudaFuncAttributeMaxDynamicSharedMemorySize, GEMM_SMEM);
    cudaFuncSetAttribute(gemm_mma<1>, cudaFuncAttributeMaxDynamicSharedMemorySize, GEMM_SMEM);
    cudaFuncSetAttribute(gemm_mma<2>, cudaFuncAttributeMaxDynamicSharedMemorySize, GEMM_SMEM);
    cudaFuncSetAttribute(flash_attn,  cudaFuncAttributeMaxDynamicSharedMemorySize, FLASH_SMEM);

    // --- residual 1: pre-norm + attention ---
    ln_kernel<<<MTOK, 256>>>(x, xn, a1, n1);

    dim3 g1024(DMODEL / 128, MTOK / 128);      // (8, 32)
    gemm_mma<0><<<g1024, 256, GEMM_SMEM>>>(xn, wq, bq, nullptr, q, MTOK, DMODEL, DMODEL,
                                           DMODEL, DMODEL, DMODEL);
    gemm_mma<0><<<g1024, 256, GEMM_SMEM>>>(xn, wk, bk, nullptr, k, MTOK, DMODEL, DMODEL,
                                           DMODEL, DMODEL, DMODEL);
    gemm_mma<0><<<g1024, 256, GEMM_SMEM>>>(xn, wv, bv, nullptr, v, MTOK, DMODEL, DMODEL,
                                           DMODEL, DMODEL, DMODEL);

    flash_attn<<<dim3(SEQ / BQ, BATCH * NHEAD), 128, FLASH_SMEM>>>(
        q, k, v, mask, attn);

    gemm_mma<2><<<g1024, 256, GEMM_SMEM>>>(attn, wo, bo, x, x1, MTOK, DMODEL, DMODEL,
                                           DMODEL, DMODEL, DMODEL);

    // --- residual 2: pre-norm + FFN ---
    ln_kernel<<<MTOK, 256>>>(x1, xn, a2, n2);

    dim3 gff1(DFF / 128, MTOK / 128);              // (32, 32)
    gemm_mma<1><<<gff1, 256, GEMM_SMEM>>>(xn, w1, b1, nullptr, ff, MTOK, DFF, DMODEL,
                                          DMODEL, DMODEL, DFF);

    dim3 gff2(DMODEL / 128, MTOK / 128);           // (8, 32)
    gemm_mma<2><<<gff2, 256, GEMM_SMEM>>>(ff, w2, b2, x1, out, MTOK, DMODEL, DFF,
                                          DFF, DFF, DMODEL);
}

// round 7
// speedup vs baseline: 3.7260x; 1.1235x over previous
#include <cuda_runtime.h>
#include <cuda_bf16.h>
#include <math.h>
#include <stdint.h>

// Problem constants
#define BATCH 2
#define SEQ   2048
#define DMODEL 1024
#define NHEAD 16
#define DK    64
#define DFF   4096
#define MTOK  (BATCH * SEQ)           // 4096 tokens
#define QKV_LD 3072
#define LN_EPS 1e-5f

// ---------------- scratch (device globals; no allocation allowed) ----------
__device__ float g_xn  [(size_t)MTOK * DMODEL];     // 16 MB (tf32-rounded)
__device__ float g_qkv [(size_t)MTOK * QKV_LD];     // 48 MB
__device__ float g_attn[(size_t)MTOK * DMODEL];     // 16 MB (tf32-rounded)
__device__ float g_x1  [(size_t)MTOK * DMODEL];     // 16 MB
__device__ float g_ff  [(size_t)MTOK * DFF];        // 64 MB (tf32-rounded)
__device__ float g_wqkv[(size_t)QKV_LD * DMODEL];   // 12 MB (rounded weights)
__device__ float g_wo_r[(size_t)DMODEL * DMODEL];   //  4 MB
__device__ float g_w1_r[(size_t)DFF * DMODEL];      // 16 MB
__device__ float g_w2_r[(size_t)DMODEL * DFF];      // 16 MB
__device__ float g_bqkv[QKV_LD];

// ============================ helpers ======================================
__device__ __forceinline__ uint32_t smem_u32(const void* p) {
    uint32_t a;
    asm("{ .reg .u64 t; cvta.to.shared.u64 t, %1; cvt.u32.u64 %0, t; }"
        : "=r"(a) : "l"(p));
    return a;
}

__device__ __forceinline__ uint32_t f2tf32(float f) {
    uint32_t r;
    asm("cvt.rna.tf32.f32 %0, %1;" : "=r"(r) : "f"(f));
    return r;
}
__device__ __forceinline__ float rtf(float f) { return __uint_as_float(f2tf32(f)); }

__device__ __forceinline__ void mma_tf32(float* c, const uint32_t* a, const uint32_t* b) {
    asm volatile(
        "mma.sync.aligned.m16n8k8.row.col.f32.tf32.tf32.f32 "
        "{%0,%1,%2,%3}, {%4,%5,%6,%7}, {%8,%9}, {%0,%1,%2,%3};"
        : "+f"(c[0]), "+f"(c[1]), "+f"(c[2]), "+f"(c[3])
        : "r"(a[0]), "r"(a[1]), "r"(a[2]), "r"(a[3]),
          "r"(b[0]), "r"(b[1]));
}

#define CP_ASYNC16(dst, src) \
    asm volatile("cp.async.cg.shared.global [%0], [%1], 16;" :: \
        "r"(dst), "l"(src) : "memory")
#define CP_COMMIT() asm volatile("cp.async.commit_group;" ::: "memory")
#define CP_WAIT(n)  asm volatile("cp.async.wait_group %0;" :: "n"(n) : "memory")

// ---------------------------------------------------------------------------
// Prep: round fp32 -> tf32 (rna) element-wise; pack qkv bias.
// ---------------------------------------------------------------------------
__global__ void round_copy(const float* __restrict__ src, float* __restrict__ dst, int n4)
{
    const int i = blockIdx.x * 256 + threadIdx.x;
    if (i < n4) {
        float4 v = ((const float4*)src)[i];
        v.x = rtf(v.x); v.y = rtf(v.y); v.z = rtf(v.z); v.w = rtf(v.w);
        ((float4*)dst)[i] = v;
    }
}

__global__ void pack_bias(const float* __restrict__ bq, const float* __restrict__ bk,
                          const float* __restrict__ bv, float* __restrict__ dst)
{
    const int i = blockIdx.x * 256 + threadIdx.x;
    if (i < DMODEL)           dst[i] = bq[i];
    else if (i < 2 * DMODEL)  dst[i] = bk[i - DMODEL];
    else if (i < 3 * DMODEL)  dst[i] = bv[i - 2 * DMODEL];
}

// ---------------------------------------------------------------------------
// LayerNorm: one block per row, torch semantics; output rounded to tf32.
// ---------------------------------------------------------------------------
__global__ void ln_kernel(const float* __restrict__ x, float* __restrict__ y,
                          const float* __restrict__ alpha, const float* __restrict__ beta)
{
    const size_t r = blockIdx.x;
    const float* xr = x + r * DMODEL;
    float* yr = y + r * DMODEL;
    const int t = threadIdx.x;

    float v[4];
    float s = 0.f, ss = 0.f;
#pragma unroll
    for (int it = 0; it < 4; it++) {
        float a = xr[t + it * 256];
        v[it] = a;
        s += a;
        ss += a * a;
    }
    __shared__ float red[2][32];
    const int lane = t & 31, wid = t >> 5;
#pragma unroll
    for (int o = 16; o > 0; o >>= 1) {
        s  += __shfl_down_sync(0xffffffffu, s,  o);
        ss += __shfl_down_sync(0xffffffffu, ss, o);
    }
    if (lane == 0) { red[0][wid] = s; red[1][wid] = ss; }
    __syncthreads();
    if (wid == 0) {
        s  = (lane < 8) ? red[0][lane] : 0.f;
        ss = (lane < 8) ? red[1][lane] : 0.f;
#pragma unroll
        for (int o = 4; o > 0; o >>= 1) {
            s  += __shfl_down_sync(0xffffffffu, s,  o);
            ss += __shfl_down_sync(0xffffffffu, ss, o);
        }
        if (lane == 0) { red[0][0] = s; red[1][0] = ss; }
    }
    __syncthreads();
    s = red[0][0]; ss = red[1][0];

    const float mean = s * (1.0f / DMODEL);
    float var = (ss - s * mean) * (1.0f / (DMODEL - 1));
    var = fmaxf(var, 0.f);
    const float inv = alpha[0] / (sqrtf(var) + LN_EPS);
    const float b0 = beta[0];
#pragma unroll
    for (int it = 0; it < 4; it++)
        yr[t + it * 256] = rtf((v[it] - mean) * inv + b0);
}

// ---------------------------------------------------------------------------
// Dense GEMM, mma.sync tf32: C[.,N](ldc) = op(A[.,K](lda) @ B[N,K](ldb)^T)
// 128x128 tile, BK=32, 128 threads = 4 warps (2x2), warp tile 64x64.
// 3-stage cp.async pipeline; operands pre-rounded to tf32 by producers.
// EPI: 0 = +bias, 1 = +bias,relu,round, 2 = +bias,+residual
// ---------------------------------------------------------------------------
#define GPAD 36
#define NSTAGE 3
#define GEMM_SMEM (NSTAGE * 2 * 128 * GPAD * 4)    // 110,592 B

template <int EPI>
__global__ __launch_bounds__(128, 2) void gemm_mma(
    const float* __restrict__ A, const float* __restrict__ B,
    const float* __restrict__ bias, const float* __restrict__ res,
    float* __restrict__ C, int K, int lda, int ldb, int ldc)
{
    extern __shared__ uint32_t gsm[];

    const int tid = threadIdx.x;
    const int lane = tid & 31, wid = tid >> 5;
    const int bm = blockIdx.y * 128, bn = blockIdx.x * 128;
    const int wm0 = (wid >> 1) * 64, wn0 = (wid & 1) * 64;
    const int g = lane >> 2, t = lane & 3;

    uint32_t abase[NSTAGE], bbase[NSTAGE];
#pragma unroll
    for (int s = 0; s < NSTAGE; s++) {
        abase[s] = smem_u32(gsm + (size_t)s * 2 * 128 * GPAD);
        bbase[s] = abase[s] + 128 * GPAD * 4;
    }

    const int NC = K >> 5;

    // loader: idx = tid + i*128 -> row = idx>>3 (0..127), slot = idx&7
#define GEMM_ISSUE(c, s) do {                                                  \
        const float* Ac_ = A + (size_t)bm * lda + (c) * 32;                    \
        const float* Bc_ = B + (size_t)bn * ldb + (c) * 32;                    \
        _Pragma("unroll")                                                      \
        for (int i_ = 0; i_ < 8; i_++) {                                       \
            const int idx_ = tid + i_ * 128;                                   \
            const int row_ = idx_ >> 3, sl_ = idx_ & 7;                        \
            const uint32_t off_ = (uint32_t)(row_ * GPAD + sl_ * 4) * 4u;      \
            CP_ASYNC16(abase[s] + off_, Ac_ + (size_t)row_ * lda + sl_ * 4);   \
            CP_ASYNC16(bbase[s] + off_, Bc_ + (size_t)row_ * ldb + sl_ * 4);   \
        }                                                                      \
        CP_COMMIT();                                                           \
    } while (0)

    GEMM_ISSUE(0, 0);
    GEMM_ISSUE(1, 1);

    float acc[4][8][4];
#pragma unroll
    for (int mt = 0; mt < 4; mt++)
#pragma unroll
        for (int nt = 0; nt < 8; nt++)
#pragma unroll
            for (int j = 0; j < 4; j++) acc[mt][nt][j] = 0.f;

    for (int c = 0; c < NC; c++) {
        const int st = c % NSTAGE;
        if (c + 2 < NC) {
            GEMM_ISSUE(c + 2, (c + 2) % NSTAGE);
            CP_WAIT(2);
        } else if (c + 1 < NC) {
            CP_WAIT(1);
        } else {
            CP_WAIT(0);
        }
        __syncthreads();

        const uint32_t* Asb = gsm + (size_t)st * 2 * 128 * GPAD;
        const uint32_t* Bsb = Asb + 128 * GPAD;
#pragma unroll
        for (int ks = 0; ks < 4; ks++) {
            const int kc = ks * 8 + t;
            uint32_t afr[4][4], bfr[8][2];
#pragma unroll
            for (int mt = 0; mt < 4; mt++) {
                const int rm = wm0 + mt * 16 + g;
                afr[mt][0] = Asb[rm * GPAD + kc];
                afr[mt][1] = Asb[(rm + 8) * GPAD + kc];
                afr[mt][2] = Asb[rm * GPAD + kc + 4];
                afr[mt][3] = Asb[(rm + 8) * GPAD + kc + 4];
            }
#pragma unroll
            for (int nt = 0; nt < 8; nt++) {
                const int rn = wn0 + nt * 8 + g;
                bfr[nt][0] = Bsb[rn * GPAD + kc];
                bfr[nt][1] = Bsb[rn * GPAD + kc + 4];
            }
#pragma unroll
            for (int mt = 0; mt < 4; mt++)
#pragma unroll
                for (int nt = 0; nt < 8; nt++)
                    mma_tf32(acc[mt][nt], afr[mt], bfr[nt]);
        }
        __syncthreads();
    }
#undef GEMM_ISSUE

#pragma unroll
    for (int mt = 0; mt < 4; mt++) {
        const int row = bm + wm0 + mt * 16 + g;
#pragma unroll
        for (int nt = 0; nt < 8; nt++) {
            const int col = bn + wn0 + nt * 8 + 2 * t;
            const float b0 = bias[col], b1 = bias[col + 1];
#pragma unroll
            for (int half = 0; half < 2; half++) {
                const int r = row + half * 8;
                float v0 = acc[mt][nt][half * 2 + 0] + b0;
                float v1 = acc[mt][nt][half * 2 + 1] + b1;
                if (EPI == 1) { v0 = rtf(fmaxf(v0, 0.f)); v1 = rtf(fmaxf(v1, 0.f)); }
                if (EPI == 2) {
                    const float* rr = res + (size_t)r * ldc + col;
                    v0 += rr[0]; v1 += rr[1];
                }
                float* cr = C + (size_t)r * ldc + col;
                cr[0] = v0; cr[1] = v1;
            }
        }
    }
}

// ---------------------------------------------------------------------------
// Flash attention: fused scores+mask+softmax+PV. Reads merged qkv buffer.
// BQ=64 queries per CTA, 128 threads = 4 warps; K/V tiles of 64 streamed.
// Output rounded to tf32 (feeds Wo GEMM).
// ---------------------------------------------------------------------------
#define BQ  64
#define BKV 64
#define FPAD 68
#define FLASH_SMEM ((4 * BQ * FPAD) * 4 + BKV * 4)

__global__ __launch_bounds__(128) void flash_attn(
    const float* __restrict__ qkv, const int* __restrict__ mask,
    float* __restrict__ out)
{
    extern __shared__ uint32_t fsm[];
    uint32_t* Qs = fsm;
    uint32_t* Ks = Qs + BQ * FPAD;
    uint32_t* Vs = Ks + BKV * FPAD;
    uint32_t* Ps = Vs + BKV * FPAD;
    int* msk = (int*)(Ps + BQ * FPAD);

    const int bh = blockIdx.y;
    const int b = bh / NHEAD, h = bh % NHEAD;
    const int qi0 = blockIdx.x * BQ;
    const float* Qg = qkv + ((size_t)(b * SEQ + qi0)) * QKV_LD + h * DK;
    const float* Kg = qkv + ((size_t)b * SEQ) * QKV_LD + DMODEL + h * DK;
    const float* Vg = qkv + ((size_t)b * SEQ) * QKV_LD + 2 * DMODEL + h * DK;

    const int tid = threadIdx.x;
    const int lane = tid & 31, wid = tid >> 5;
    const int g = lane >> 2, t = lane & 3;
    const int ar = wid * 16 + g;
    const int c2 = 2 * t;

#pragma unroll
    for (int i = 0; i < 8; i++) {
        const int idx = tid + i * 128;
        const int row = idx >> 4, c4 = idx & 15;
        float4 qv = *(const float4*)(Qg + (size_t)row * QKV_LD + c4 * 4);
        uint32_t* dst = Qs + row * FPAD + c4 * 4;
        dst[0] = f2tf32(qv.x * 0.125f);
        dst[1] = f2tf32(qv.y * 0.125f);
        dst[2] = f2tf32(qv.z * 0.125f);
        dst[3] = f2tf32(qv.w * 0.125f);
    }

    float m0 = -INFINITY, m1 = -INFINITY, l0 = 0.f, l1 = 0.f;
    float o[8][4];
#pragma unroll
    for (int nt = 0; nt < 8; nt++)
#pragma unroll
        for (int j = 0; j < 4; j++) o[nt][j] = 0.f;

    for (int jt = 0; jt < SEQ; jt += BKV) {
#pragma unroll
        for (int i = 0; i < 8; i++) {
            const int idx = tid + i * 128;
            const int row = idx >> 4, c4 = idx & 15;
            float4 kv = *(const float4*)(Kg + (size_t)(jt + row) * QKV_LD + c4 * 4);
            float4 vv = *(const float4*)(Vg + (size_t)(jt + row) * QKV_LD + c4 * 4);
            uint32_t* kd = Ks + row * FPAD + c4 * 4;
            kd[0] = f2tf32(kv.x); kd[1] = f2tf32(kv.y);
            kd[2] = f2tf32(kv.z); kd[3] = f2tf32(kv.w);
            uint32_t* vd = Vs + row * FPAD + c4 * 4;
            vd[0] = f2tf32(vv.x); vd[1] = f2tf32(vv.y);
            vd[2] = f2tf32(vv.z); vd[3] = f2tf32(vv.w);
        }
        if (tid < BKV) msk[tid] = mask[(size_t)b * SEQ + jt + tid];
        __syncthreads();

        float s[8][4];
#pragma unroll
        for (int nt = 0; nt < 8; nt++)
#pragma unroll
            for (int j = 0; j < 4; j++) s[nt][j] = 0.f;

#pragma unroll
        for (int ks = 0; ks < 8; ks++) {
            const int kc = ks * 8 + t;
            uint32_t a[4];
            a[0] = Qs[ar * FPAD + kc];
            a[1] = Qs[(ar + 8) * FPAD + kc];
            a[2] = Qs[ar * FPAD + kc + 4];
            a[3] = Qs[(ar + 8) * FPAD + kc + 4];
#pragma unroll
            for (int nt = 0; nt < 8; nt++) {
                const int rn = nt * 8 + g;
                uint32_t bb[2] = { Ks[rn * FPAD + kc], Ks[rn * FPAD + kc + 4] };
                mma_tf32(s[nt], a, bb);
            }
        }

#pragma unroll
        for (int nt = 0; nt < 8; nt++) {
            const int c0 = nt * 8 + c2;
            if (msk[c0] == 0)     { s[nt][0] = -1e9f; s[nt][2] = -1e9f; }
            if (msk[c0 + 1] == 0) { s[nt][1] = -1e9f; s[nt][3] = -1e9f; }
        }

        float mx0 = -INFINITY, mx1 = -INFINITY;
#pragma unroll
        for (int nt = 0; nt < 8; nt++) {
            mx0 = fmaxf(mx0, fmaxf(s[nt][0], s[nt][1]));
            mx1 = fmaxf(mx1, fmaxf(s[nt][2], s[nt][3]));
        }
        mx0 = fmaxf(mx0, __shfl_xor_sync(0xffffffffu, mx0, 1));
        mx0 = fmaxf(mx0, __shfl_xor_sync(0xffffffffu, mx0, 2));
        mx1 = fmaxf(mx1, __shfl_xor_sync(0xffffffffu, mx1, 1));
        mx1 = fmaxf(mx1, __shfl_xor_sync(0xffffffffu, mx1, 2));

        const float mn0 = fmaxf(m0, mx0), mn1 = fmaxf(m1, mx1);
        const float sc0 = __expf(m0 - mn0), sc1 = __expf(m1 - mn1);

        float sum0 = 0.f, sum1 = 0.f;
#pragma unroll
        for (int nt = 0; nt < 8; nt++) {
            const float p0 = __expf(s[nt][0] - mn0);
            const float p1 = __expf(s[nt][1] - mn0);
            const float p2 = __expf(s[nt][2] - mn1);
            const float p3 = __expf(s[nt][3] - mn1);
            sum0 += p0 + p1; sum1 += p2 + p3;
            const int c0 = nt * 8 + c2;
            Ps[ar * FPAD + c0]           = f2tf32(p0);
            Ps[ar * FPAD + c0 + 1]       = f2tf32(p1);
            Ps[(ar + 8) * FPAD + c0]     = f2tf32(p2);
            Ps[(ar + 8) * FPAD + c0 + 1] = f2tf32(p3);
            o[nt][0] *= sc0; o[nt][1] *= sc0;
            o[nt][2] *= sc1; o[nt][3] *= sc1;
        }
        sum0 += __shfl_xor_sync(0xffffffffu, sum0, 1);
        sum0 += __shfl_xor_sync(0xffffffffu, sum0, 2);
        sum1 += __shfl_xor_sync(0xffffffffu, sum1, 1);
        sum1 += __shfl_xor_sync(0xffffffffu, sum1, 2);
        l0 = l0 * sc0 + sum0;
        l1 = l1 * sc1 + sum1;
        m0 = mn0; m1 = mn1;
        __syncwarp();

#pragma unroll
        for (int ks = 0; ks < 8; ks++) {
            const int kc = ks * 8 + t;
            uint32_t a[4];
            a[0] = Ps[ar * FPAD + kc];
            a[1] = Ps[(ar + 8) * FPAD + kc];
            a[2] = Ps[ar * FPAD + kc + 4];
            a[3] = Ps[(ar + 8) * FPAD + kc + 4];
#pragma unroll
            for (int nt = 0; nt < 8; nt++) {
                const int rn = nt * 8 + g;
                uint32_t bb[2] = { Vs[kc * FPAD + rn], Vs[(kc + 4) * FPAD + rn] };
                mma_tf32(o[nt], a, bb);
            }
        }
        __syncthreads();
    }

    const float inv0 = 1.f / l0, inv1 = 1.f / l1;
    float* Og = out + ((size_t)(b * SEQ + qi0)) * DMODEL + h * DK;
#pragma unroll
    for (int nt = 0; nt < 8; nt++) {
        const int c0 = nt * 8 + c2;
        Og[(size_t)ar * DMODEL + c0]           = rtf(o[nt][0] * inv0);
        Og[(size_t)ar * DMODEL + c0 + 1]       = rtf(o[nt][1] * inv0);
        Og[(size_t)(ar + 8) * DMODEL + c0]     = rtf(o[nt][2] * inv1);
        Og[(size_t)(ar + 8) * DMODEL + c0 + 1] = rtf(o[nt][3] * inv1);
    }
}

// ---------------------------------------------------------------------------
// Launch sequence
// ---------------------------------------------------------------------------
extern "C" void kernel_launch(void* const* d_in, const int* in_sizes, int n_in,
                              void* d_out, int out_size)
{
    const float* x    = (const float*)d_in[0];
    const int*   mask = (const int*)  d_in[1];
    const float* wq   = (const float*)d_in[2];
    const float* bq   = (const float*)d_in[3];
    const float* wk   = (const float*)d_in[4];
    const float* bk   = (const float*)d_in[5];
    const float* wv   = (const float*)d_in[6];
    const float* bv   = (const float*)d_in[7];
    const float* wo   = (const float*)d_in[8];
    const float* bo   = (const float*)d_in[9];
    const float* w1   = (const float*)d_in[10];
    const float* b1   = (const float*)d_in[11];
    const float* w2   = (const float*)d_in[12];
    const float* b2   = (const float*)d_in[13];
    const float* a1   = (const float*)d_in[14];
    const float* n1   = (const float*)d_in[15];
    const float* a2   = (const float*)d_in[16];
    const float* n2   = (const float*)d_in[17];
    float* out = (float*)d_out;

    float *xn, *qkv, *attn, *x1, *ff, *wqkv, *wo_r, *w1_r, *w2_r, *bqkv;
    cudaGetSymbolAddress((void**)&xn,   g_xn);
    cudaGetSymbolAddress((void**)&qkv,  g_qkv);
    cudaGetSymbolAddress((void**)&attn, g_attn);
    cudaGetSymbolAddress((void**)&x1,   g_x1);
    cudaGetSymbolAddress((void**)&ff,   g_ff);
    cudaGetSymbolAddress((void**)&wqkv, g_wqkv);
    cudaGetSymbolAddress((void**)&wo_r, g_wo_r);
    cudaGetSymbolAddress((void**)&w1_r, g_w1_r);
    cudaGetSymbolAddress((void**)&w2_r, g_w2_r);
    cudaGetSymbolAddress((void**)&bqkv, g_bqkv);

    cudaFuncSetAttribute(gemm_mma<0>, cudaFuncAttributeMaxDynamicSharedMemorySize, GEMM_SMEM);
    cudaFuncSetAttribute(gemm_mma<1>, cudaFuncAttributeMaxDynamicSharedMemorySize, GEMM_SMEM);
    cudaFuncSetAttribute(gemm_mma<2>, cudaFuncAttributeMaxDynamicSharedMemorySize, GEMM_SMEM);
    cudaFuncSetAttribute(flash_attn,  cudaFuncAttributeMaxDynamicSharedMemorySize, FLASH_SMEM);

    // --- prep: rna-round weights into scratch, pack qkv bias ---
    const int NW1 = DMODEL * DMODEL / 4;       // 262144 float4
    round_copy<<<NW1 / 256, 256>>>(wq, wqkv,                 NW1);
    round_copy<<<NW1 / 256, 256>>>(wk, wqkv + DMODEL*DMODEL, NW1);
    round_copy<<<NW1 / 256, 256>>>(wv, wqkv + 2*DMODEL*DMODEL, NW1);
    round_copy<<<NW1 / 256, 256>>>(wo, wo_r, NW1);
    const int NW4 = DFF * DMODEL / 4;          // 1048576 float4
    round_copy<<<NW4 / 256, 256>>>(w1, w1_r, NW4);
    round_copy<<<NW4 / 256, 256>>>(w2, w2_r, NW4);
    pack_bias<<<QKV_LD / 256, 256>>>(bq, bk, bv, bqkv);

    // --- residual 1: pre-norm + attention ---
    ln_kernel<<<MTOK, 256>>>(x, xn, a1, n1);

    gemm_mma<0><<<dim3(QKV_LD / 128, MTOK / 128), 128, GEMM_SMEM>>>(
        xn, wqkv, bqkv, nullptr, qkv, DMODEL, DMODEL, DMODEL, QKV_LD);

    flash_attn<<<dim3(SEQ / BQ, BATCH * NHEAD), 128, FLASH_SMEM>>>(qkv, mask, attn);

    gemm_mma<2><<<dim3(DMODEL / 128, MTOK / 128), 128, GEMM_SMEM>>>(
        attn, wo_r, bo, x, x1, DMODEL, DMODEL, DMODEL, DMODEL);

    // --- residual 2: pre-norm + FFN ---
    ln_kernel<<<MTOK, 256>>>(x1, xn, a2, n2);

    gemm_mma<1><<<dim3(DFF / 128, MTOK / 128), 128, GEMM_SMEM>>>(
        xn, w1_r, b1, nullptr, ff, DMODEL, DMODEL, DMODEL, DFF);

    gemm_mma<2><<<dim3(DMODEL / 128, MTOK / 128), 128, GEMM_SMEM>>>(
        ff, w2_r, b2, x1, out, DFF, DFF, DFF, DMODEL);
}